// round 3
// baseline (speedup 1.0000x reference)
#include <cuda_runtime.h>

#define TB 128
typedef unsigned long long ull;

// fast sigmoid / tanh via MUFU exp; rel err ~1e-6.
__device__ __forceinline__ float fsig(float x) {
    float e = __expf(-x);
    return __fdividef(1.0f, 1.0f + e);
}
__device__ __forceinline__ float ftanh(float x) {
    x = fminf(fmaxf(x, -15.0f), 15.0f);
    float e = __expf(-2.0f * x);
    return __fdividef(1.0f - e, 1.0f + e);
}
__device__ __forceinline__ ull pack2(float lo, float hi) {
    ull r; asm("mov.b64 %0, {%1, %2};" : "=l"(r) : "f"(lo), "f"(hi)); return r;
}
__device__ __forceinline__ ull dup2(float v) {
    ull r; asm("mov.b64 %0, {%1, %1};" : "=l"(r) : "f"(v)); return r;
}
__device__ __forceinline__ void unpack2(ull v, float& lo, float& hi) {
    asm("mov.b64 {%0, %1}, %2;" : "=f"(lo), "=f"(hi) : "l"(v));
}
#define FMA2(acc, w, a) asm("fma.rn.f32x2 %0, %1, %2, %3;" : "=l"(acc) : "l"(w), "l"(a), "l"(acc))

extern __shared__ float s_raw[];
// smem float offsets:
//   s_w   [0,    8192)  : 2048 float4, gate-interleaved weights W4[m][j'], j'=jj*4+q, m=0..63 (feat|h)
//   s_b4  [8192, 8320)  : 32 float4 bias (j' interleave)
//   s_co  [8320, 8448)  : 32 float4 coW  (j' interleave)
//   s_cf  [8448, 8704)  : 32 rows x 8 floats cf (m' = mm*4+q interleave)
//   s_cob [8704, 8708)
#define OFF_B4 8192
#define OFF_CO 8320
#define OFF_CF 8448
#define OFF_COB 8704

// One LSTM step for a 4-thread quad. Thread q owns hidden units j = q*8+jj.
// feat computed split (8 per thread) from replicated X; activations shared via shfl.
__device__ __forceinline__ void lstm_step_quad(
    int q, int src_base, const float* __restrict__ X,
    float* __restrict__ h_loc, float* __restrict__ c)
{
    // Phase A: my 8 feature values (rows m = q*8+mm, stored at m' = mm*4+q)
    float feat_loc[8];
#pragma unroll
    for (int mm = 0; mm < 8; mm++) {
        const float* cf = s_raw + OFF_CF + (mm * 4 + q) * 8;
        float4 a = *reinterpret_cast<const float4*>(cf);
        float4 b = *reinterpret_cast<const float4*>(cf + 4);
        float acc = b.z;
        acc = fmaf(a.x, X[0], acc);
        acc = fmaf(a.y, X[1], acc);
        acc = fmaf(a.z, X[2], acc);
        acc = fmaf(a.w, X[3], acc);
        acc = fmaf(b.x, X[4], acc);
        acc = fmaf(b.y, X[5], acc);
        feat_loc[mm] = ftanh(acc);
    }

    // Phase B: gates for my 8 j's, packed (i,f) and (g,o) f32x2 accumulators.
    ull acc_if[8], acc_go[8];
    {
        const float4* b4 = reinterpret_cast<const float4*>(s_raw + OFF_B4);
#pragma unroll
        for (int jj = 0; jj < 8; jj++) {
            float4 b = b4[jj * 4 + q];
            acc_if[jj] = pack2(b.x, b.y);
            acc_go[jj] = pack2(b.z, b.w);
        }
    }
    const ulonglong2* w2 = reinterpret_cast<const ulonglong2*>(s_raw);
#pragma unroll
    for (int g = 0; g < 4; g++) {
        int src = src_base + g;
#pragma unroll
        for (int mm = 0; mm < 8; mm++) {
            ull a2 = dup2(__shfl_sync(0xffffffffu, feat_loc[mm], src));
            const ulonglong2* row = w2 + (g * 8 + mm) * 32;
#pragma unroll
            for (int jj = 0; jj < 8; jj++) {
                ulonglong2 w = row[jj * 4 + q];
                FMA2(acc_if[jj], w.x, a2);
                FMA2(acc_go[jj], w.y, a2);
            }
        }
    }
#pragma unroll
    for (int g = 0; g < 4; g++) {
        int src = src_base + g;
#pragma unroll
        for (int mm = 0; mm < 8; mm++) {
            ull a2 = dup2(__shfl_sync(0xffffffffu, h_loc[mm], src));
            const ulonglong2* row = w2 + (32 + g * 8 + mm) * 32;
#pragma unroll
            for (int jj = 0; jj < 8; jj++) {
                ulonglong2 w = row[jj * 4 + q];
                FMA2(acc_if[jj], w.x, a2);
                FMA2(acc_go[jj], w.y, a2);
            }
        }
    }

    // Phase C: nonlinearities, c/h update (registers)
#pragma unroll
    for (int jj = 0; jj < 8; jj++) {
        float gi, gf, gg, go;
        unpack2(acc_if[jj], gi, gf);
        unpack2(acc_go[jj], gg, go);
        float ig = fsig(gi), fg = fsig(gf);
        float g_ = ftanh(gg), og = fsig(go);
        float cj = fmaf(fg, c[jj], ig * g_);
        c[jj] = cj;
        h_loc[jj] = og * ftanh(cj);
    }
}

__global__ void __launch_bounds__(TB, 3) kalman_lstm_kernel(
    const float* __restrict__ hist,
    const float* __restrict__ p_psx, const float* __restrict__ p_psy,
    const float* __restrict__ p_vsx, const float* __restrict__ p_vsy,
    const float* __restrict__ p_asx, const float* __restrict__ p_asy,
    const float* __restrict__ p_jerk, const float* __restrict__ p_coefG,
    const float* __restrict__ p_GR,
    const float* __restrict__ cfW, const float* __restrict__ cfb,
    const float* __restrict__ Wih, const float* __restrict__ Whh,
    const float* __restrict__ bih, const float* __restrict__ bhh,
    const float* __restrict__ coW, const float* __restrict__ cob,
    float* __restrict__ out,
    int B, int T, int LP)
{
    const int tid = threadIdx.x;

    // ---- stage weights: gate-interleaved float4, j' = jj*4+q so a quad's
    // loads hit 64 contiguous bytes (conflict-free broadcast) ----
    for (int idx = tid; idx < 2048; idx += TB) {
        int m = idx >> 5;          // 0..63 : [feat(0..31) | h(32..63)]
        int jp = idx & 31;
        int qq = jp & 3, jj = jp >> 2;
        int j = qq * 8 + jj;
        const float* W = (m < 32) ? Wih : Whh;
        int mm = m & 31;
        reinterpret_cast<float4*>(s_raw)[idx] = make_float4(
            W[j * 32 + mm], W[(32 + j) * 32 + mm],
            W[(64 + j) * 32 + mm], W[(96 + j) * 32 + mm]);
    }
    if (tid < 32) {
        int jp = tid, qq = jp & 3, jj = jp >> 2;
        int j = qq * 8 + jj;
        reinterpret_cast<float4*>(s_raw + OFF_B4)[jp] = make_float4(
            bih[j] + bhh[j],           bih[32 + j] + bhh[32 + j],
            bih[64 + j] + bhh[64 + j], bih[96 + j] + bhh[96 + j]);
        reinterpret_cast<float4*>(s_raw + OFF_CO)[jp] = make_float4(
            coW[j], coW[32 + j], coW[64 + j], coW[96 + j]);
        int m = qq * 8 + jj;       // cf row owner mapping (m' = mm*4+q)
#pragma unroll
        for (int k = 0; k < 6; k++) s_raw[OFF_CF + jp * 8 + k] = cfW[m * 6 + k];
        s_raw[OFF_CF + jp * 8 + 6] = cfb[m];
        s_raw[OFF_CF + jp * 8 + 7] = 0.0f;
    }
    if (tid < 4) s_raw[OFF_COB + tid] = cob[tid];
    __syncthreads();

    const int lane = tid & 31;
    const int q = lane & 3;
    const int src_base = lane & ~3;
    const int e_raw = (blockIdx.x * TB + tid) >> 2;
    const bool valid = e_raw < B;
    const int e = valid ? e_raw : (B - 1);

    const float dt = 0.2f, hd2 = 0.02f;
    const float g0 = (float)(0.2 * 0.2 * 0.2 / 6.0);
    const float g1 = 0.02f;
    const float g2 = 0.2f;

    float tg[6];
#pragma unroll
    for (int i = 0; i < 6; i++) tg[i] = tanhf(p_coefG[i]);
    const float jk0 = p_jerk[0], jk1 = p_jerk[1];
    const float Ghx0 = g0 * tg[0] * jk0, Ghx1 = g1 * tg[1] * jk0, Ghx2 = g2 * tg[2] * jk0;
    const float Ghy0 = g0 * tg[3] * jk1, Ghy1 = g1 * tg[4] * jk1, Ghy2 = g2 * tg[5] * jk1;
    const float gt0 = g0 * tg[0], gt1 = g1 * tg[1], gt2 = g2 * tg[2];
    const float gt3 = g0 * tg[3], gt4 = g1 * tg[4], gt5 = g2 * tg[5];
    const float gr0 = p_GR[0], gr1 = p_GR[1];
    const float R00 = gr0 * gr0, R01 = gr0 * gr1, R11 = gr1 * gr1;

    const float2* hist2 = reinterpret_cast<const float2*>(hist);

    // ---- Kalman init (replicated across the quad) ----
    float2 z0 = hist2[e];
    float2 z1 = hist2[(size_t)B + e];
    float X[6];
    X[0] = z0.x; X[1] = (z1.x - z0.x) / dt; X[2] = 0.0f;
    X[3] = (z1.y - z0.y) / dt; X[4] = 0.0f; X[5] = 0.0f;

    float P[6][6];
#pragma unroll
    for (int i = 0; i < 6; i++)
#pragma unroll
        for (int j = 0; j < 6; j++) P[i][j] = 0.0f;
    {
        float d0 = p_psx[0], d1 = p_vsx[0], d2 = p_asx[0];
        float d3 = p_psy[0], d4 = p_vsy[0], d5 = p_asy[0];
        P[0][0] = d0 * d0; P[1][1] = d1 * d1; P[2][2] = d2 * d2;
        P[3][3] = d3 * d3; P[4][4] = d4 * d4; P[5][5] = d5 * d5;
    }

    float h_loc[8], c[8];
#pragma unroll
    for (int m = 0; m < 8; m++) { h_loc[m] = 0.0f; c[m] = 0.0f; }

    // ================= history filtering =================
#pragma unroll 1
    for (int t = 1; t < T; t++) {
        lstm_step_quad(q, src_base, X, h_loc, c);

        // X = F X
        {
            float x0 = X[0] + dt * X[1] + hd2 * X[2];
            float x1 = X[1] + dt * X[2];
            float x3 = X[3] + dt * X[4] + hd2 * X[5];
            float x4 = X[4] + dt * X[5];
            X[0] = x0; X[1] = x1; X[3] = x3; X[4] = x4;
        }
        // P = F P F^T + Q_hist
#pragma unroll
        for (int cc = 0; cc < 6; cc++) {
            P[0][cc] += dt * P[1][cc] + hd2 * P[2][cc];
            P[1][cc] += dt * P[2][cc];
            P[3][cc] += dt * P[4][cc] + hd2 * P[5][cc];
            P[4][cc] += dt * P[5][cc];
        }
#pragma unroll
        for (int r = 0; r < 6; r++) {
            P[r][0] += dt * P[r][1] + hd2 * P[r][2];
            P[r][1] += dt * P[r][2];
            P[r][3] += dt * P[r][4] + hd2 * P[r][5];
            P[r][4] += dt * P[r][5];
        }
        {
            float gx[3] = {Ghx0, Ghx1, Ghx2}, gy[3] = {Ghy0, Ghy1, Ghy2};
#pragma unroll
            for (int a = 0; a < 3; a++)
#pragma unroll
                for (int bb = 0; bb < 3; bb++) {
                    P[a][bb]         += gx[a] * gx[bb];
                    P[3 + a][3 + bb] += gy[a] * gy[bb];
                }
        }
        // measurement update
        float2 z = hist2[(size_t)t * B + e];
        float yx = z.x - X[0], yy = z.y - X[3];
        float S00 = P[0][0] + R00, S01 = P[0][3] + R01;
        float S10 = P[3][0] + R01, S11 = P[3][3] + R11;
        float rdet = 1.0f / (S00 * S11 - S01 * S10);
        float si00 =  S11 * rdet, si01 = -S01 * rdet;
        float si10 = -S10 * rdet, si11 =  S00 * rdet;
        float K0[6], K1[6];
#pragma unroll
        for (int i = 0; i < 6; i++) {
            K0[i] = P[i][0] * si00 + P[i][3] * si10;
            K1[i] = P[i][0] * si01 + P[i][3] * si11;
        }
#pragma unroll
        for (int i = 0; i < 6; i++) X[i] += K0[i] * yx + K1[i] * yy;
        float r0[6], r3[6];
#pragma unroll
        for (int j = 0; j < 6; j++) { r0[j] = P[0][j]; r3[j] = P[3][j]; }
#pragma unroll
        for (int i = 0; i < 6; i++)
#pragma unroll
            for (int j = 0; j < 6; j++) P[i][j] -= K0[i] * r0[j] + K1[i] * r3[j];
        float q0[6], q3[6];
#pragma unroll
        for (int i = 0; i < 6; i++) { q0[i] = P[i][0]; q3[i] = P[i][3]; }
#pragma unroll
        for (int i = 0; i < 6; i++)
#pragma unroll
            for (int j = 0; j < 6; j++) P[i][j] -= q0[i] * K0[j] + q3[i] * K1[j];
#pragma unroll
        for (int i = 0; i < 6; i++) {
            float kr0 = K0[i] * R00 + K1[i] * R01;
            float kr1 = K0[i] * R01 + K1[i] * R11;
#pragma unroll
            for (int j = 0; j < 6; j++) P[i][j] += kr0 * K0[j] + kr1 * K1[j];
        }
    }

    // ================= prediction =================
#pragma unroll 1
    for (int t = 0; t < LP; t++) {
        lstm_step_quad(q, src_base, X, h_loc, c);

        // command = h @ coW^T + cob : partial over my 8 j's, quad shfl-xor reduce
        float c0 = 0.f, c1 = 0.f, c2 = 0.f, c3 = 0.f;
        const float4* co4 = reinterpret_cast<const float4*>(s_raw + OFF_CO);
#pragma unroll
        for (int jj = 0; jj < 8; jj++) {
            float4 w = co4[jj * 4 + q];
            c0 = fmaf(w.x, h_loc[jj], c0);
            c1 = fmaf(w.y, h_loc[jj], c1);
            c2 = fmaf(w.z, h_loc[jj], c2);
            c3 = fmaf(w.w, h_loc[jj], c3);
        }
        c0 += __shfl_xor_sync(0xffffffffu, c0, 1);
        c1 += __shfl_xor_sync(0xffffffffu, c1, 1);
        c2 += __shfl_xor_sync(0xffffffffu, c2, 1);
        c3 += __shfl_xor_sync(0xffffffffu, c3, 1);
        c0 += __shfl_xor_sync(0xffffffffu, c0, 2);
        c1 += __shfl_xor_sync(0xffffffffu, c1, 2);
        c2 += __shfl_xor_sync(0xffffffffu, c2, 2);
        c3 += __shfl_xor_sync(0xffffffffu, c3, 2);
        float cm0 = c0 + s_raw[OFF_COB + 0];
        float cm1 = c1 + s_raw[OFF_COB + 1];
        float cm2 = c2 + s_raw[OFF_COB + 2];
        float cm3 = c3 + s_raw[OFF_COB + 3];

        // X = F X + B cmd[:2]
        {
            float x0 = X[0] + dt * X[1] + hd2 * X[2] + g0 * cm0;
            float x1 = X[1] + dt * X[2] + g1 * cm0;
            float x2 = X[2] + g2 * cm0;
            float x3 = X[3] + dt * X[4] + hd2 * X[5] + g0 * cm1;
            float x4 = X[4] + dt * X[5] + g1 * cm1;
            float x5 = X[5] + g2 * cm1;
            X[0] = x0; X[1] = x1; X[2] = x2; X[3] = x3; X[4] = x4; X[5] = x5;
        }
        float Gs[6] = {gt0 * cm2, gt1 * cm2, gt2 * cm2, gt3 * cm3, gt4 * cm3, gt5 * cm3};
        // P = F P F^T + Gs Gs^T
#pragma unroll
        for (int cc = 0; cc < 6; cc++) {
            P[0][cc] += dt * P[1][cc] + hd2 * P[2][cc];
            P[1][cc] += dt * P[2][cc];
            P[3][cc] += dt * P[4][cc] + hd2 * P[5][cc];
            P[4][cc] += dt * P[5][cc];
        }
#pragma unroll
        for (int r = 0; r < 6; r++) {
            P[r][0] += dt * P[r][1] + hd2 * P[r][2];
            P[r][1] += dt * P[r][2];
            P[r][3] += dt * P[r][4] + hd2 * P[r][5];
            P[r][4] += dt * P[r][5];
        }
#pragma unroll
        for (int i = 0; i < 6; i++)
#pragma unroll
            for (int j = 0; j < 6; j++) P[i][j] += Gs[i] * Gs[j];

        // outputs: lane q writes field q; lane 0 also writes rho (field 4)
        if (valid) {
            float sx = sqrtf(P[0][0]);
            float sy = sqrtf(P[3][3]);
            float rho = __fdividef(P[0][3] + P[3][0], 2.0f * sx * sy);
            size_t o = ((size_t)t * B + e) * 5;
            float v = (q == 0) ? X[0] : (q == 1) ? X[3] : (q == 2) ? sx : sy;
            out[o + q] = v;
            if (q == 0) out[o + 4] = rho;
        }
    }
}

extern "C" void kernel_launch(void* const* d_in, const int* in_sizes, int n_in,
                              void* d_out, int out_size) {
    const float* hist  = (const float*)d_in[0];
    const float* psx   = (const float*)d_in[1];
    const float* psy   = (const float*)d_in[2];
    const float* vsx   = (const float*)d_in[3];
    const float* vsy   = (const float*)d_in[4];
    const float* asx   = (const float*)d_in[5];
    const float* asy   = (const float*)d_in[6];
    const float* jerk  = (const float*)d_in[7];
    const float* coefG = (const float*)d_in[8];
    const float* GR    = (const float*)d_in[9];
    const float* cfW   = (const float*)d_in[10];
    const float* cfb   = (const float*)d_in[11];
    const float* Wih   = (const float*)d_in[12];
    const float* Whh   = (const float*)d_in[13];
    const float* bih   = (const float*)d_in[14];
    const float* bhh   = (const float*)d_in[15];
    const float* coW   = (const float*)d_in[16];
    const float* cob   = (const float*)d_in[17];
    float* out = (float*)d_out;

    const int T = 16;
    int B  = in_sizes[0] / (2 * T);
    int LP = out_size / (B * 5);

    size_t smem = (size_t)8720 * sizeof(float);  // 34880 bytes
    cudaFuncSetAttribute(kalman_lstm_kernel,
                         cudaFuncAttributeMaxDynamicSharedMemorySize, (int)smem);

    long long threads = (long long)B * 4;
    int grid = (int)((threads + TB - 1) / TB);
    kalman_lstm_kernel<<<grid, TB, smem>>>(
        hist, psx, psy, vsx, vsy, asx, asy, jerk, coefG, GR,
        cfW, cfb, Wih, Whh, bih, bhh, coW, cob, out, B, T, LP);
}

// round 4
// speedup vs baseline: 1.7480x; 1.7480x over previous
#include <cuda_runtime.h>

#define TB 128
typedef unsigned long long ull;

// fast sigmoid / tanh via MUFU; rel err ~1e-6.
__device__ __forceinline__ float fsig(float x) {
    float e = __expf(-x);
    return __fdividef(1.0f, 1.0f + e);
}
__device__ __forceinline__ float ftanh(float x) {
    x = fminf(fmaxf(x, -15.0f), 15.0f);
    float e = __expf(-2.0f * x);
    return __fdividef(1.0f - e, 1.0f + e);
}
__device__ __forceinline__ ull pack2(float lo, float hi) {
    ull r; asm("mov.b64 %0, {%1, %2};" : "=l"(r) : "f"(lo), "f"(hi)); return r;
}
__device__ __forceinline__ ull dup2(float v) {
    ull r; asm("mov.b64 %0, {%1, %1};" : "=l"(r) : "f"(v)); return r;
}
__device__ __forceinline__ void unpack2(ull v, float& lo, float& hi) {
    asm("mov.b64 {%0, %1}, %2;" : "=f"(lo), "=f"(hi) : "l"(v));
}
#define FMA2(acc, w, a) asm("fma.rn.f32x2 %0, %1, %2, %3;" : "=l"(acc) : "l"(w), "l"(a), "l"(acc))

// float-unit offsets in dynamic smem
#define OFF_W   0      // ulonglong2[2048]: gate-pair weights [half*32+m][j]
#define OFF_B   8192   // ulonglong2[32]  : bias pairs per j
#define OFF_CO  8320   // float4[32]      : coW columns per m
#define OFF_CF  8448   // float[32*8]     : cf rows (6w + b + pad)
#define OFF_COB 8704   // float[4]
#define OFF_H   8720   // float[2 pair][2 buf][32 m][32 lane]
#define SMEM_FLOATS (8720 + 4096)

extern __shared__ float s_raw[];

// One LSTM step; this warp (half w of the pair) computes gates j = w*16+jj.
// All weight loads are warp-uniform broadcasts; h exchanged via smem columns.
__device__ __forceinline__ void lstm_step(
    int w, int lane, int rbase, int wbase,
    const float* __restrict__ X, float* __restrict__ c)
{
    // feat = tanh(cf_W @ X + cf_b), replicated in both warps of the pair
    float feat[32];
#pragma unroll 1
    for (int m = 0; m < 32; m++) {
        const float* cf = s_raw + OFF_CF + m * 8;
        float4 a = *reinterpret_cast<const float4*>(cf);
        float4 b = *reinterpret_cast<const float4*>(cf + 4);
        float acc = b.z;
        acc = fmaf(a.x, X[0], acc);
        acc = fmaf(a.y, X[1], acc);
        acc = fmaf(a.z, X[2], acc);
        acc = fmaf(a.w, X[3], acc);
        acc = fmaf(b.x, X[4], acc);
        acc = fmaf(b.y, X[5], acc);
        feat[m] = ftanh(acc);
    }

    // gate accumulators: (i,f) and (g,o) packed f32x2 for my 16 j's
    ull acc_if[16], acc_go[16];
    const ulonglong2* sb = reinterpret_cast<const ulonglong2*>(s_raw + OFF_B);
#pragma unroll
    for (int jj = 0; jj < 16; jj++) {
        ulonglong2 b = sb[w * 16 + jj];
        acc_if[jj] = b.x; acc_go[jj] = b.y;
    }

    const ulonglong2* w2 = reinterpret_cast<const ulonglong2*>(s_raw + OFF_W);
    // input half: feat
#pragma unroll 1
    for (int m = 0; m < 32; m++) {
        ull a2 = dup2(feat[m]);
        const ulonglong2* row = w2 + m * 32 + w * 16;
#pragma unroll
        for (int jj = 0; jj < 16; jj++) {
            ulonglong2 ww = row[jj];
            FMA2(acc_if[jj], ww.x, a2);
            FMA2(acc_go[jj], ww.y, a2);
        }
    }
    // recurrent half: h from smem (coalesced per-element column)
    const float* hin = s_raw + OFF_H + rbase + lane;
#pragma unroll 1
    for (int m = 0; m < 32; m++) {
        ull a2 = dup2(hin[m * 32]);
        const ulonglong2* row = w2 + (32 + m) * 32 + w * 16;
#pragma unroll
        for (int jj = 0; jj < 16; jj++) {
            ulonglong2 ww = row[jj];
            FMA2(acc_if[jj], ww.x, a2);
            FMA2(acc_go[jj], ww.y, a2);
        }
    }

    // nonlinearities; c in regs; h_new -> smem write buffer
    float* hout = s_raw + OFF_H + wbase + w * 16 * 32 + lane;
#pragma unroll
    for (int jj = 0; jj < 16; jj++) {
        float gi, gf, gg, go;
        unpack2(acc_if[jj], gi, gf);
        unpack2(acc_go[jj], gg, go);
        float ig = fsig(gi), fg = fsig(gf);
        float g_ = ftanh(gg), og = fsig(go);
        float cj = fmaf(fg, c[jj], ig * g_);
        c[jj] = cj;
        hout[jj * 32] = og * ftanh(cj);
    }
}

__global__ void __launch_bounds__(TB, 3) kalman_lstm_kernel(
    const float* __restrict__ hist,
    const float* __restrict__ p_psx, const float* __restrict__ p_psy,
    const float* __restrict__ p_vsx, const float* __restrict__ p_vsy,
    const float* __restrict__ p_asx, const float* __restrict__ p_asy,
    const float* __restrict__ p_jerk, const float* __restrict__ p_coefG,
    const float* __restrict__ p_GR,
    const float* __restrict__ cfW, const float* __restrict__ cfb,
    const float* __restrict__ Wih, const float* __restrict__ Whh,
    const float* __restrict__ bih, const float* __restrict__ bhh,
    const float* __restrict__ coW, const float* __restrict__ cob,
    float* __restrict__ out,
    int B, int T, int LP)
{
    const int tid = threadIdx.x;

    // ---- stage weights as gate-pair ulonglong2, index (half*32+m)*32 + j ----
    for (int idx = tid; idx < 2048; idx += TB) {
        int hm = idx >> 5;          // half*32 + m
        int j  = idx & 31;
        int half = hm >> 5, m = hm & 31;
        const float* W = half ? Whh : Wih;
        ulonglong2 v;
        v.x = pack2(W[j * 32 + m],        W[(32 + j) * 32 + m]);
        v.y = pack2(W[(64 + j) * 32 + m], W[(96 + j) * 32 + m]);
        reinterpret_cast<ulonglong2*>(s_raw + OFF_W)[idx] = v;
    }
    if (tid < 32) {
        int j = tid;
        ulonglong2 b;
        b.x = pack2(bih[j] + bhh[j],           bih[32 + j] + bhh[32 + j]);
        b.y = pack2(bih[64 + j] + bhh[64 + j], bih[96 + j] + bhh[96 + j]);
        reinterpret_cast<ulonglong2*>(s_raw + OFF_B)[j] = b;
        reinterpret_cast<float4*>(s_raw + OFF_CO)[j] = make_float4(
            coW[j], coW[32 + j], coW[64 + j], coW[96 + j]);
#pragma unroll
        for (int k = 0; k < 6; k++) s_raw[OFF_CF + j * 8 + k] = cfW[j * 6 + k];
        s_raw[OFF_CF + j * 8 + 6] = cfb[j];
        s_raw[OFF_CF + j * 8 + 7] = 0.0f;
    }
    if (tid < 4) s_raw[OFF_COB + tid] = cob[tid];

    const int warpid = tid >> 5;
    const int pair = warpid >> 1;        // 0..1 within block
    const int w    = warpid & 1;         // gate half
    const int lane = tid & 31;

    // zero h read-buffer (buf 0) for my pair
#pragma unroll
    for (int jj = 0; jj < 16; jj++)
        s_raw[OFF_H + pair * 2048 + (w * 16 + jj) * 32 + lane] = 0.0f;
    __syncthreads();

    int rbase = pair * 2048;             // read buffer base (floats, rel OFF_H)
    int wbase = rbase + 1024;            // write buffer base

    const int e_raw = (blockIdx.x * 2 + pair) * 32 + lane;
    const bool valid = e_raw < B;
    const int e = valid ? e_raw : (B - 1);

    const float dt = 0.2f, hd2 = 0.02f;
    const float g0 = (float)(0.2 * 0.2 * 0.2 / 6.0);
    const float g1 = 0.02f;
    const float g2 = 0.2f;

    float tg[6];
#pragma unroll
    for (int i = 0; i < 6; i++) tg[i] = tanhf(p_coefG[i]);
    const float jk0 = p_jerk[0], jk1 = p_jerk[1];
    const float Ghx0 = g0 * tg[0] * jk0, Ghx1 = g1 * tg[1] * jk0, Ghx2 = g2 * tg[2] * jk0;
    const float Ghy0 = g0 * tg[3] * jk1, Ghy1 = g1 * tg[4] * jk1, Ghy2 = g2 * tg[5] * jk1;
    const float gt0 = g0 * tg[0], gt1 = g1 * tg[1], gt2 = g2 * tg[2];
    const float gt3 = g0 * tg[3], gt4 = g1 * tg[4], gt5 = g2 * tg[5];
    const float gr0 = p_GR[0], gr1 = p_GR[1];
    const float R00 = gr0 * gr0, R01 = gr0 * gr1, R11 = gr1 * gr1;

    const float2* hist2 = reinterpret_cast<const float2*>(hist);

    // ---- Kalman init (replicated in both warps of the pair) ----
    float2 z0 = hist2[e];
    float2 z1 = hist2[(size_t)B + e];
    float X[6];
    X[0] = z0.x; X[1] = (z1.x - z0.x) / dt; X[2] = 0.0f;
    X[3] = (z1.y - z0.y) / dt; X[4] = 0.0f; X[5] = 0.0f;

    float P[6][6];
#pragma unroll
    for (int i = 0; i < 6; i++)
#pragma unroll
        for (int j = 0; j < 6; j++) P[i][j] = 0.0f;
    {
        float d0 = p_psx[0], d1 = p_vsx[0], d2 = p_asx[0];
        float d3 = p_psy[0], d4 = p_vsy[0], d5 = p_asy[0];
        P[0][0] = d0 * d0; P[1][1] = d1 * d1; P[2][2] = d2 * d2;
        P[3][3] = d3 * d3; P[4][4] = d4 * d4; P[5][5] = d5 * d5;
    }

    float c[16];
#pragma unroll
    for (int jj = 0; jj < 16; jj++) c[jj] = 0.0f;

    // ================= history filtering =================
#pragma unroll 1
    for (int t = 1; t < T; t++) {
        lstm_step(w, lane, rbase, wbase, X, c);
        __syncthreads();
        int tmp = rbase; rbase = wbase; wbase = tmp;

        // X = F X
        {
            float x0 = X[0] + dt * X[1] + hd2 * X[2];
            float x1 = X[1] + dt * X[2];
            float x3 = X[3] + dt * X[4] + hd2 * X[5];
            float x4 = X[4] + dt * X[5];
            X[0] = x0; X[1] = x1; X[3] = x3; X[4] = x4;
        }
        // P = F P F^T + Q_hist
#pragma unroll
        for (int cc = 0; cc < 6; cc++) {
            P[0][cc] += dt * P[1][cc] + hd2 * P[2][cc];
            P[1][cc] += dt * P[2][cc];
            P[3][cc] += dt * P[4][cc] + hd2 * P[5][cc];
            P[4][cc] += dt * P[5][cc];
        }
#pragma unroll
        for (int r = 0; r < 6; r++) {
            P[r][0] += dt * P[r][1] + hd2 * P[r][2];
            P[r][1] += dt * P[r][2];
            P[r][3] += dt * P[r][4] + hd2 * P[r][5];
            P[r][4] += dt * P[r][5];
        }
        {
            float gx[3] = {Ghx0, Ghx1, Ghx2}, gy[3] = {Ghy0, Ghy1, Ghy2};
#pragma unroll
            for (int a = 0; a < 3; a++)
#pragma unroll
                for (int bb = 0; bb < 3; bb++) {
                    P[a][bb]         += gx[a] * gx[bb];
                    P[3 + a][3 + bb] += gy[a] * gy[bb];
                }
        }
        // measurement update
        float2 z = hist2[(size_t)t * B + e];
        float yx = z.x - X[0], yy = z.y - X[3];
        float S00 = P[0][0] + R00, S01 = P[0][3] + R01;
        float S10 = P[3][0] + R01, S11 = P[3][3] + R11;
        float rdet = 1.0f / (S00 * S11 - S01 * S10);
        float si00 =  S11 * rdet, si01 = -S01 * rdet;
        float si10 = -S10 * rdet, si11 =  S00 * rdet;
        float K0[6], K1[6];
#pragma unroll
        for (int i = 0; i < 6; i++) {
            K0[i] = P[i][0] * si00 + P[i][3] * si10;
            K1[i] = P[i][0] * si01 + P[i][3] * si11;
        }
#pragma unroll
        for (int i = 0; i < 6; i++) X[i] += K0[i] * yx + K1[i] * yy;
        float r0[6], r3[6];
#pragma unroll
        for (int j = 0; j < 6; j++) { r0[j] = P[0][j]; r3[j] = P[3][j]; }
#pragma unroll
        for (int i = 0; i < 6; i++)
#pragma unroll
            for (int j = 0; j < 6; j++) P[i][j] -= K0[i] * r0[j] + K1[i] * r3[j];
        float q0[6], q3[6];
#pragma unroll
        for (int i = 0; i < 6; i++) { q0[i] = P[i][0]; q3[i] = P[i][3]; }
#pragma unroll
        for (int i = 0; i < 6; i++)
#pragma unroll
            for (int j = 0; j < 6; j++) P[i][j] -= q0[i] * K0[j] + q3[i] * K1[j];
#pragma unroll
        for (int i = 0; i < 6; i++) {
            float kr0 = K0[i] * R00 + K1[i] * R01;
            float kr1 = K0[i] * R01 + K1[i] * R11;
#pragma unroll
            for (int j = 0; j < 6; j++) P[i][j] += kr0 * K0[j] + kr1 * K1[j];
        }
    }

    // ================= prediction =================
#pragma unroll 1
    for (int t = 0; t < LP; t++) {
        lstm_step(w, lane, rbase, wbase, X, c);
        __syncthreads();

        // command = coW @ h_new + cob, read from just-written buffer
        float cm0 = s_raw[OFF_COB + 0], cm1 = s_raw[OFF_COB + 1];
        float cm2 = s_raw[OFF_COB + 2], cm3 = s_raw[OFF_COB + 3];
        {
            const float* hb = s_raw + OFF_H + wbase + lane;
            const float4* co4 = reinterpret_cast<const float4*>(s_raw + OFF_CO);
#pragma unroll 1
            for (int m = 0; m < 32; m++) {
                float4 cw = co4[m];
                float hm = hb[m * 32];
                cm0 = fmaf(cw.x, hm, cm0);
                cm1 = fmaf(cw.y, hm, cm1);
                cm2 = fmaf(cw.z, hm, cm2);
                cm3 = fmaf(cw.w, hm, cm3);
            }
        }
        int tmp = rbase; rbase = wbase; wbase = tmp;

        // X = F X + B cmd[:2]
        {
            float x0 = X[0] + dt * X[1] + hd2 * X[2] + g0 * cm0;
            float x1 = X[1] + dt * X[2] + g1 * cm0;
            float x2 = X[2] + g2 * cm0;
            float x3 = X[3] + dt * X[4] + hd2 * X[5] + g0 * cm1;
            float x4 = X[4] + dt * X[5] + g1 * cm1;
            float x5 = X[5] + g2 * cm1;
            X[0] = x0; X[1] = x1; X[2] = x2; X[3] = x3; X[4] = x4; X[5] = x5;
        }
        float Gs[6] = {gt0 * cm2, gt1 * cm2, gt2 * cm2, gt3 * cm3, gt4 * cm3, gt5 * cm3};
        // P = F P F^T + Gs Gs^T
#pragma unroll
        for (int cc = 0; cc < 6; cc++) {
            P[0][cc] += dt * P[1][cc] + hd2 * P[2][cc];
            P[1][cc] += dt * P[2][cc];
            P[3][cc] += dt * P[4][cc] + hd2 * P[5][cc];
            P[4][cc] += dt * P[5][cc];
        }
#pragma unroll
        for (int r = 0; r < 6; r++) {
            P[r][0] += dt * P[r][1] + hd2 * P[r][2];
            P[r][1] += dt * P[r][2];
            P[r][3] += dt * P[r][4] + hd2 * P[r][5];
            P[r][4] += dt * P[r][5];
        }
#pragma unroll
        for (int i = 0; i < 6; i++)
#pragma unroll
            for (int j = 0; j < 6; j++) P[i][j] += Gs[i] * Gs[j];

        // outputs (warp half 0 writes; both halves hold identical X/P)
        if (valid && w == 0) {
            float sx = sqrtf(P[0][0]);
            float sy = sqrtf(P[3][3]);
            float rho = __fdividef(P[0][3] + P[3][0], 2.0f * sx * sy);
            size_t o = ((size_t)t * B + e) * 5;
            out[o + 0] = X[0];
            out[o + 1] = X[3];
            out[o + 2] = sx;
            out[o + 3] = sy;
            out[o + 4] = rho;
        }
    }
}

extern "C" void kernel_launch(void* const* d_in, const int* in_sizes, int n_in,
                              void* d_out, int out_size) {
    const float* hist  = (const float*)d_in[0];
    const float* psx   = (const float*)d_in[1];
    const float* psy   = (const float*)d_in[2];
    const float* vsx   = (const float*)d_in[3];
    const float* vsy   = (const float*)d_in[4];
    const float* asx   = (const float*)d_in[5];
    const float* asy   = (const float*)d_in[6];
    const float* jerk  = (const float*)d_in[7];
    const float* coefG = (const float*)d_in[8];
    const float* GR    = (const float*)d_in[9];
    const float* cfW   = (const float*)d_in[10];
    const float* cfb   = (const float*)d_in[11];
    const float* Wih   = (const float*)d_in[12];
    const float* Whh   = (const float*)d_in[13];
    const float* bih   = (const float*)d_in[14];
    const float* bhh   = (const float*)d_in[15];
    const float* coW   = (const float*)d_in[16];
    const float* cob   = (const float*)d_in[17];
    float* out = (float*)d_out;

    const int T = 16;
    int B  = in_sizes[0] / (2 * T);
    int LP = out_size / (B * 5);

    size_t smem = (size_t)SMEM_FLOATS * sizeof(float);  // 51264 bytes
    cudaFuncSetAttribute(kalman_lstm_kernel,
                         cudaFuncAttributeMaxDynamicSharedMemorySize, (int)smem);

    int groups = (B + 31) / 32;          // 32-element groups
    int grid = (groups + 1) / 2;         // 2 groups (pairs) per block
    kalman_lstm_kernel<<<grid, TB, smem>>>(
        hist, psx, psy, vsx, vsy, asx, asy, jerk, coefG, GR,
        cfW, cfb, Wih, Whh, bih, bhh, coW, cob, out, B, T, LP);
}

// round 5
// speedup vs baseline: 1.9935x; 1.1405x over previous
#include <cuda_runtime.h>

#define TB 128
typedef unsigned long long ull;

// fast sigmoid / tanh via MUFU; rel err ~1e-6.
__device__ __forceinline__ float fsig(float x) {
    float e = __expf(-x);
    return __fdividef(1.0f, 1.0f + e);
}
__device__ __forceinline__ float ftanh(float x) {
    x = fminf(fmaxf(x, -15.0f), 15.0f);
    float e = __expf(-2.0f * x);
    return __fdividef(1.0f - e, 1.0f + e);
}
__device__ __forceinline__ ull pack2(float lo, float hi) {
    ull r; asm("mov.b64 %0, {%1, %2};" : "=l"(r) : "f"(lo), "f"(hi)); return r;
}
__device__ __forceinline__ ull dup2(float v) {
    ull r; asm("mov.b64 %0, {%1, %1};" : "=l"(r) : "f"(v)); return r;
}
__device__ __forceinline__ void unpack2(ull v, float& lo, float& hi) {
    asm("mov.b64 {%0, %1}, %2;" : "=f"(lo), "=f"(hi) : "l"(v));
}
// tied accumulator: no copy MOVs around the packed FMA
#define FMA2(acc, w, a) asm("fma.rn.f32x2 %0, %1, %2, %0;" : "+l"(acc) : "l"(w), "l"(a))

// float-unit offsets in dynamic smem
#define OFF_W   0      // ulonglong2[2048]: gate-pair weights [half*32+m][j]
#define OFF_B   8192   // ulonglong2[32]  : bias pairs per j
#define OFF_CO  8320   // float4[32]      : coW columns per m
#define OFF_CF  8448   // float[32*8]     : cf rows (6w + b + pad)
#define OFF_COB 8704   // float[4]
#define OFF_H   8720   // float[2 pair][2 buf][32 m][32 lane]
#define SMEM_FLOATS (8720 + 4096)

extern __shared__ float s_raw[];

// One LSTM step; this warp (half w of the pair) computes gates j = w*16+jj.
// All weight loads are warp-uniform broadcasts; h exchanged via smem columns.
__device__ __forceinline__ void lstm_step(
    int w, int lane, int rbase, int wbase,
    const float* __restrict__ X, float* __restrict__ c)
{
    // feat = tanh(cf_W @ X + cf_b), replicated in both warps of the pair
    float feat[32];
    {
        const float4* cf = reinterpret_cast<const float4*>(s_raw + OFF_CF);
#pragma unroll 2
        for (int m = 0; m < 32; m++) {
            float4 a = cf[2 * m];
            float4 b = cf[2 * m + 1];
            float acc = b.z;
            acc = fmaf(a.x, X[0], acc);
            acc = fmaf(a.y, X[1], acc);
            acc = fmaf(a.z, X[2], acc);
            acc = fmaf(a.w, X[3], acc);
            acc = fmaf(b.x, X[4], acc);
            acc = fmaf(b.y, X[5], acc);
            feat[m] = ftanh(acc);
        }
    }

    // gate accumulators: (i,f) and (g,o) packed f32x2 for my 16 j's
    ull acc_if[16], acc_go[16];
    {
        const ulonglong2* sb = reinterpret_cast<const ulonglong2*>(s_raw + OFF_B) + w * 16;
#pragma unroll
        for (int jj = 0; jj < 16; jj++) {
            ulonglong2 b = sb[jj];
            acc_if[jj] = b.x; acc_go[jj] = b.y;
        }
    }

    // input half: feat (weights broadcast from smem)
    {
        const ulonglong2* row = reinterpret_cast<const ulonglong2*>(s_raw + OFF_W) + w * 16;
#pragma unroll 2
        for (int m = 0; m < 32; m++) {
            ull a2 = dup2(feat[m]);
#pragma unroll
            for (int jj = 0; jj < 16; jj++) {
                ulonglong2 ww = row[jj];
                FMA2(acc_if[jj], ww.x, a2);
                FMA2(acc_go[jj], ww.y, a2);
            }
            row += 32;
        }
        // recurrent half: h from smem (coalesced per-element column)
        const float* hin = s_raw + OFF_H + rbase + lane;
#pragma unroll 2
        for (int m = 0; m < 32; m++) {
            ull a2 = dup2(hin[m * 32]);
#pragma unroll
            for (int jj = 0; jj < 16; jj++) {
                ulonglong2 ww = row[jj];
                FMA2(acc_if[jj], ww.x, a2);
                FMA2(acc_go[jj], ww.y, a2);
            }
            row += 32;
        }
    }

    // nonlinearities; c in regs; h_new -> smem write buffer
    float* hout = s_raw + OFF_H + wbase + w * 16 * 32 + lane;
#pragma unroll
    for (int jj = 0; jj < 16; jj++) {
        float gi, gf, gg, go;
        unpack2(acc_if[jj], gi, gf);
        unpack2(acc_go[jj], gg, go);
        float ig = fsig(gi), fg = fsig(gf);
        float g_ = ftanh(gg), og = fsig(go);
        float cj = fmaf(fg, c[jj], ig * g_);
        c[jj] = cj;
        hout[jj * 32] = og * ftanh(cj);
    }
}

__global__ void __launch_bounds__(TB, 3) kalman_lstm_kernel(
    const float* __restrict__ hist,
    const float* __restrict__ p_psx, const float* __restrict__ p_psy,
    const float* __restrict__ p_vsx, const float* __restrict__ p_vsy,
    const float* __restrict__ p_asx, const float* __restrict__ p_asy,
    const float* __restrict__ p_jerk, const float* __restrict__ p_coefG,
    const float* __restrict__ p_GR,
    const float* __restrict__ cfW, const float* __restrict__ cfb,
    const float* __restrict__ Wih, const float* __restrict__ Whh,
    const float* __restrict__ bih, const float* __restrict__ bhh,
    const float* __restrict__ coW, const float* __restrict__ cob,
    float* __restrict__ out,
    int B, int T, int LP)
{
    const int tid = threadIdx.x;

    // ---- stage weights as gate-pair ulonglong2, index (half*32+m)*32 + j ----
    for (int idx = tid; idx < 2048; idx += TB) {
        int hm = idx >> 5;          // half*32 + m
        int j  = idx & 31;
        int half = hm >> 5, m = hm & 31;
        const float* W = half ? Whh : Wih;
        ulonglong2 v;
        v.x = pack2(W[j * 32 + m],        W[(32 + j) * 32 + m]);
        v.y = pack2(W[(64 + j) * 32 + m], W[(96 + j) * 32 + m]);
        reinterpret_cast<ulonglong2*>(s_raw + OFF_W)[idx] = v;
    }
    if (tid < 32) {
        int j = tid;
        ulonglong2 b;
        b.x = pack2(bih[j] + bhh[j],           bih[32 + j] + bhh[32 + j]);
        b.y = pack2(bih[64 + j] + bhh[64 + j], bih[96 + j] + bhh[96 + j]);
        reinterpret_cast<ulonglong2*>(s_raw + OFF_B)[j] = b;
        reinterpret_cast<float4*>(s_raw + OFF_CO)[j] = make_float4(
            coW[j], coW[32 + j], coW[64 + j], coW[96 + j]);
#pragma unroll
        for (int k = 0; k < 6; k++) s_raw[OFF_CF + j * 8 + k] = cfW[j * 6 + k];
        s_raw[OFF_CF + j * 8 + 6] = cfb[j];
        s_raw[OFF_CF + j * 8 + 7] = 0.0f;
    }
    if (tid < 4) s_raw[OFF_COB + tid] = cob[tid];

    const int warpid = tid >> 5;
    const int pair = warpid >> 1;        // 0..1 within block
    const int w    = warpid & 1;         // gate half
    const int lane = tid & 31;

    // zero h read-buffer (buf 0) for my pair
#pragma unroll
    for (int jj = 0; jj < 16; jj++)
        s_raw[OFF_H + pair * 2048 + (w * 16 + jj) * 32 + lane] = 0.0f;
    __syncthreads();

    int rbase = pair * 2048;             // read buffer base (floats, rel OFF_H)
    int wbase = rbase + 1024;            // write buffer base

    const int e_raw = (blockIdx.x * 2 + pair) * 32 + lane;
    const bool valid = e_raw < B;
    const int e = valid ? e_raw : (B - 1);

    const float dt = 0.2f, hd2 = 0.02f;
    const float g0 = (float)(0.2 * 0.2 * 0.2 / 6.0);
    const float g1 = 0.02f;
    const float g2 = 0.2f;

    float tg[6];
#pragma unroll
    for (int i = 0; i < 6; i++) tg[i] = tanhf(p_coefG[i]);
    const float jk0 = p_jerk[0], jk1 = p_jerk[1];
    const float Ghx0 = g0 * tg[0] * jk0, Ghx1 = g1 * tg[1] * jk0, Ghx2 = g2 * tg[2] * jk0;
    const float Ghy0 = g0 * tg[3] * jk1, Ghy1 = g1 * tg[4] * jk1, Ghy2 = g2 * tg[5] * jk1;
    const float gt0 = g0 * tg[0], gt1 = g1 * tg[1], gt2 = g2 * tg[2];
    const float gt3 = g0 * tg[3], gt4 = g1 * tg[4], gt5 = g2 * tg[5];
    const float gr0 = p_GR[0], gr1 = p_GR[1];
    const float R00 = gr0 * gr0, R01 = gr0 * gr1, R11 = gr1 * gr1;

    const float2* hist2 = reinterpret_cast<const float2*>(hist);

    // ---- Kalman init (replicated in both warps of the pair) ----
    float2 z0 = hist2[e];
    float2 z1 = hist2[(size_t)B + e];
    float X[6];
    X[0] = z0.x; X[1] = (z1.x - z0.x) / dt; X[2] = 0.0f;
    X[3] = (z1.y - z0.y) / dt; X[4] = 0.0f; X[5] = 0.0f;

    float P[6][6];
#pragma unroll
    for (int i = 0; i < 6; i++)
#pragma unroll
        for (int j = 0; j < 6; j++) P[i][j] = 0.0f;
    {
        float d0 = p_psx[0], d1 = p_vsx[0], d2 = p_asx[0];
        float d3 = p_psy[0], d4 = p_vsy[0], d5 = p_asy[0];
        P[0][0] = d0 * d0; P[1][1] = d1 * d1; P[2][2] = d2 * d2;
        P[3][3] = d3 * d3; P[4][4] = d4 * d4; P[5][5] = d5 * d5;
    }

    float c[16];
#pragma unroll
    for (int jj = 0; jj < 16; jj++) c[jj] = 0.0f;

    // ================= history filtering =================
#pragma unroll 1
    for (int t = 1; t < T; t++) {
        lstm_step(w, lane, rbase, wbase, X, c);
        __syncthreads();
        int tmp = rbase; rbase = wbase; wbase = tmp;

        // X = F X
        {
            float x0 = X[0] + dt * X[1] + hd2 * X[2];
            float x1 = X[1] + dt * X[2];
            float x3 = X[3] + dt * X[4] + hd2 * X[5];
            float x4 = X[4] + dt * X[5];
            X[0] = x0; X[1] = x1; X[3] = x3; X[4] = x4;
        }
        // P = F P F^T + Q_hist
#pragma unroll
        for (int cc = 0; cc < 6; cc++) {
            P[0][cc] += dt * P[1][cc] + hd2 * P[2][cc];
            P[1][cc] += dt * P[2][cc];
            P[3][cc] += dt * P[4][cc] + hd2 * P[5][cc];
            P[4][cc] += dt * P[5][cc];
        }
#pragma unroll
        for (int r = 0; r < 6; r++) {
            P[r][0] += dt * P[r][1] + hd2 * P[r][2];
            P[r][1] += dt * P[r][2];
            P[r][3] += dt * P[r][4] + hd2 * P[r][5];
            P[r][4] += dt * P[r][5];
        }
        {
            float gx[3] = {Ghx0, Ghx1, Ghx2}, gy[3] = {Ghy0, Ghy1, Ghy2};
#pragma unroll
            for (int a = 0; a < 3; a++)
#pragma unroll
                for (int bb = 0; bb < 3; bb++) {
                    P[a][bb]         += gx[a] * gx[bb];
                    P[3 + a][3 + bb] += gy[a] * gy[bb];
                }
        }
        // measurement update
        float2 z = hist2[(size_t)t * B + e];
        float yx = z.x - X[0], yy = z.y - X[3];
        float S00 = P[0][0] + R00, S01 = P[0][3] + R01;
        float S10 = P[3][0] + R01, S11 = P[3][3] + R11;
        float rdet = 1.0f / (S00 * S11 - S01 * S10);
        float si00 =  S11 * rdet, si01 = -S01 * rdet;
        float si10 = -S10 * rdet, si11 =  S00 * rdet;
        float K0[6], K1[6];
#pragma unroll
        for (int i = 0; i < 6; i++) {
            K0[i] = P[i][0] * si00 + P[i][3] * si10;
            K1[i] = P[i][0] * si01 + P[i][3] * si11;
        }
#pragma unroll
        for (int i = 0; i < 6; i++) X[i] += K0[i] * yx + K1[i] * yy;
        float r0[6], r3[6];
#pragma unroll
        for (int j = 0; j < 6; j++) { r0[j] = P[0][j]; r3[j] = P[3][j]; }
#pragma unroll
        for (int i = 0; i < 6; i++)
#pragma unroll
            for (int j = 0; j < 6; j++) P[i][j] -= K0[i] * r0[j] + K1[i] * r3[j];
        float q0[6], q3[6];
#pragma unroll
        for (int i = 0; i < 6; i++) { q0[i] = P[i][0]; q3[i] = P[i][3]; }
#pragma unroll
        for (int i = 0; i < 6; i++)
#pragma unroll
            for (int j = 0; j < 6; j++) P[i][j] -= q0[i] * K0[j] + q3[i] * K1[j];
#pragma unroll
        for (int i = 0; i < 6; i++) {
            float kr0 = K0[i] * R00 + K1[i] * R01;
            float kr1 = K0[i] * R01 + K1[i] * R11;
#pragma unroll
            for (int j = 0; j < 6; j++) P[i][j] += kr0 * K0[j] + kr1 * K1[j];
        }
    }

    // ================= prediction =================
#pragma unroll 1
    for (int t = 0; t < LP; t++) {
        lstm_step(w, lane, rbase, wbase, X, c);
        __syncthreads();

        // command = coW @ h_new + cob, read from just-written buffer
        float cm0 = s_raw[OFF_COB + 0], cm1 = s_raw[OFF_COB + 1];
        float cm2 = s_raw[OFF_COB + 2], cm3 = s_raw[OFF_COB + 3];
        {
            const float* hb = s_raw + OFF_H + wbase + lane;
            const float4* co4 = reinterpret_cast<const float4*>(s_raw + OFF_CO);
#pragma unroll 2
            for (int m = 0; m < 32; m++) {
                float4 cw = co4[m];
                float hm = hb[m * 32];
                cm0 = fmaf(cw.x, hm, cm0);
                cm1 = fmaf(cw.y, hm, cm1);
                cm2 = fmaf(cw.z, hm, cm2);
                cm3 = fmaf(cw.w, hm, cm3);
            }
        }
        int tmp = rbase; rbase = wbase; wbase = tmp;

        // X = F X + B cmd[:2]
        {
            float x0 = X[0] + dt * X[1] + hd2 * X[2] + g0 * cm0;
            float x1 = X[1] + dt * X[2] + g1 * cm0;
            float x2 = X[2] + g2 * cm0;
            float x3 = X[3] + dt * X[4] + hd2 * X[5] + g0 * cm1;
            float x4 = X[4] + dt * X[5] + g1 * cm1;
            float x5 = X[5] + g2 * cm1;
            X[0] = x0; X[1] = x1; X[2] = x2; X[3] = x3; X[4] = x4; X[5] = x5;
        }
        float Gs[6] = {gt0 * cm2, gt1 * cm2, gt2 * cm2, gt3 * cm3, gt4 * cm3, gt5 * cm3};
        // P = F P F^T + Gs Gs^T
#pragma unroll
        for (int cc = 0; cc < 6; cc++) {
            P[0][cc] += dt * P[1][cc] + hd2 * P[2][cc];
            P[1][cc] += dt * P[2][cc];
            P[3][cc] += dt * P[4][cc] + hd2 * P[5][cc];
            P[4][cc] += dt * P[5][cc];
        }
#pragma unroll
        for (int r = 0; r < 6; r++) {
            P[r][0] += dt * P[r][1] + hd2 * P[r][2];
            P[r][1] += dt * P[r][2];
            P[r][3] += dt * P[r][4] + hd2 * P[r][5];
            P[r][4] += dt * P[r][5];
        }
#pragma unroll
        for (int i = 0; i < 6; i++)
#pragma unroll
            for (int j = 0; j < 6; j++) P[i][j] += Gs[i] * Gs[j];

        // outputs (warp half 0 writes; both halves hold identical X/P)
        if (valid && w == 0) {
            float sx = sqrtf(P[0][0]);
            float sy = sqrtf(P[3][3]);
            float rho = __fdividef(P[0][3] + P[3][0], 2.0f * sx * sy);
            size_t o = ((size_t)t * B + e) * 5;
            out[o + 0] = X[0];
            out[o + 1] = X[3];
            out[o + 2] = sx;
            out[o + 3] = sy;
            out[o + 4] = rho;
        }
    }
}

extern "C" void kernel_launch(void* const* d_in, const int* in_sizes, int n_in,
                              void* d_out, int out_size) {
    const float* hist  = (const float*)d_in[0];
    const float* psx   = (const float*)d_in[1];
    const float* psy   = (const float*)d_in[2];
    const float* vsx   = (const float*)d_in[3];
    const float* vsy   = (const float*)d_in[4];
    const float* asx   = (const float*)d_in[5];
    const float* asy   = (const float*)d_in[6];
    const float* jerk  = (const float*)d_in[7];
    const float* coefG = (const float*)d_in[8];
    const float* GR    = (const float*)d_in[9];
    const float* cfW   = (const float*)d_in[10];
    const float* cfb   = (const float*)d_in[11];
    const float* Wih   = (const float*)d_in[12];
    const float* Whh   = (const float*)d_in[13];
    const float* bih   = (const float*)d_in[14];
    const float* bhh   = (const float*)d_in[15];
    const float* coW   = (const float*)d_in[16];
    const float* cob   = (const float*)d_in[17];
    float* out = (float*)d_out;

    const int T = 16;
    int B  = in_sizes[0] / (2 * T);
    int LP = out_size / (B * 5);

    size_t smem = (size_t)SMEM_FLOATS * sizeof(float);  // 51264 bytes
    cudaFuncSetAttribute(kalman_lstm_kernel,
                         cudaFuncAttributeMaxDynamicSharedMemorySize, (int)smem);

    int groups = (B + 31) / 32;          // 32-element groups
    int grid = (groups + 1) / 2;         // 2 groups (pairs) per block
    kalman_lstm_kernel<<<grid, TB, smem>>>(
        hist, psx, psy, vsx, vsy, asx, asy, jerk, coefG, GR,
        cfW, cfb, Wih, Whh, bih, bhh, coW, cob, out, B, T, LP);
}

// round 6
// speedup vs baseline: 2.7416x; 1.3753x over previous
#include <cuda_runtime.h>

#define TB 128
typedef unsigned long long ull;

// fast sigmoid / tanh via MUFU; rel err ~1e-6; clamp-free (inf/0 limits correct).
__device__ __forceinline__ float fsig(float x) {
    float e = __expf(-x);
    return __fdividef(1.0f, 1.0f + e);
}
__device__ __forceinline__ float ftanh(float x) {
    float e = __expf(2.0f * x);            // +inf for large x, 0 for very negative
    return 1.0f - __fdividef(2.0f, e + 1.0f);
}
__device__ __forceinline__ ull pack2(float lo, float hi) {
    ull r; asm("mov.b64 %0, {%1, %2};" : "=l"(r) : "f"(lo), "f"(hi)); return r;
}
__device__ __forceinline__ ull dup2(float v) {
    ull r; asm("mov.b64 %0, {%1, %1};" : "=l"(r) : "f"(v)); return r;
}
__device__ __forceinline__ void unpack2(ull v, float& lo, float& hi) {
    asm("mov.b64 {%0, %1}, %2;" : "=f"(lo), "=f"(hi) : "l"(v));
}
// tied accumulator: no copy MOVs around the packed FMA
#define FMA2(acc, w, a) asm("fma.rn.f32x2 %0, %1, %2, %0;" : "+l"(acc) : "l"(w), "l"(a))

// per-pair barrier (64 threads), ids 1 and 2
#define PAIR_SYNC(p) asm volatile("bar.sync %0, 64;" :: "r"((p) + 1) : "memory")

// float-unit offsets in dynamic smem
#define OFF_W   0      // ulonglong2[2048]: gate-pair weights [half*32+m][j]
#define OFF_B   8192   // ulonglong2[32]  : bias pairs per j
#define OFF_CO  8320   // float4[32]      : coW columns per m
#define OFF_CF  8448   // float[32*8]     : cf rows (6w + b + pad)
#define OFF_COB 8704   // float[4]
#define OFF_H   8720   // float[2 pair][2 buf][32 m][32 lane]
#define SMEM_FLOATS (8720 + 4096)

extern __shared__ float s_raw[];

// One LSTM step; this warp (half w of the pair) computes gates j = w*16+jj.
// feat is computed on the fly in chunks of 8 (8-reg rolling buffer).
__device__ __forceinline__ void lstm_step(
    int w, int lane, int rbase, int wbase,
    const float* __restrict__ X, float* __restrict__ c)
{
    // gate accumulators: (i,f) and (g,o) packed f32x2 for my 16 j's
    ull acc_if[16], acc_go[16];
    {
        const ulonglong2* sb = reinterpret_cast<const ulonglong2*>(s_raw + OFF_B) + w * 16;
#pragma unroll
        for (int jj = 0; jj < 16; jj++) {
            ulonglong2 b = sb[jj];
            acc_if[jj] = b.x; acc_go[jj] = b.y;
        }
    }

    const ulonglong2* row = reinterpret_cast<const ulonglong2*>(s_raw + OFF_W) + w * 16;
    const float4* cf = reinterpret_cast<const float4*>(s_raw + OFF_CF);

    // input half: feat chunks of 8, fused
#pragma unroll 1
    for (int mb = 0; mb < 4; mb++) {
        float f8[8];
#pragma unroll
        for (int k = 0; k < 8; k++) {
            float4 a = cf[0];
            float4 b = cf[1];
            cf += 2;
            float acc = b.z;
            acc = fmaf(a.x, X[0], acc);
            acc = fmaf(a.y, X[1], acc);
            acc = fmaf(a.z, X[2], acc);
            acc = fmaf(a.w, X[3], acc);
            acc = fmaf(b.x, X[4], acc);
            acc = fmaf(b.y, X[5], acc);
            f8[k] = ftanh(acc);
        }
#pragma unroll
        for (int k = 0; k < 8; k++) {
            ull a2 = dup2(f8[k]);
#pragma unroll
            for (int jj = 0; jj < 16; jj++) {
                ulonglong2 ww = row[jj];
                FMA2(acc_if[jj], ww.x, a2);
                FMA2(acc_go[jj], ww.y, a2);
            }
            row += 32;
        }
    }
    // recurrent half: h from smem (coalesced per-element column)
    {
        const float* hin = s_raw + OFF_H + rbase + lane;
#pragma unroll 2
        for (int m = 0; m < 32; m++) {
            ull a2 = dup2(hin[m * 32]);
#pragma unroll
            for (int jj = 0; jj < 16; jj++) {
                ulonglong2 ww = row[jj];
                FMA2(acc_if[jj], ww.x, a2);
                FMA2(acc_go[jj], ww.y, a2);
            }
            row += 32;
        }
    }

    // nonlinearities; c in regs; h_new -> smem write buffer
    float* hout = s_raw + OFF_H + wbase + w * 16 * 32 + lane;
#pragma unroll
    for (int jj = 0; jj < 16; jj++) {
        float gi, gf, gg, go;
        unpack2(acc_if[jj], gi, gf);
        unpack2(acc_go[jj], gg, go);
        float ig = fsig(gi), fg = fsig(gf);
        float g_ = ftanh(gg), og = fsig(go);
        float cj = fmaf(fg, c[jj], ig * g_);
        c[jj] = cj;
        hout[jj * 32] = og * ftanh(cj);
    }
}

__global__ void __launch_bounds__(TB, 4) kalman_lstm_kernel(
    const float* __restrict__ hist,
    const float* __restrict__ p_psx, const float* __restrict__ p_psy,
    const float* __restrict__ p_vsx, const float* __restrict__ p_vsy,
    const float* __restrict__ p_asx, const float* __restrict__ p_asy,
    const float* __restrict__ p_jerk, const float* __restrict__ p_coefG,
    const float* __restrict__ p_GR,
    const float* __restrict__ cfW, const float* __restrict__ cfb,
    const float* __restrict__ Wih, const float* __restrict__ Whh,
    const float* __restrict__ bih, const float* __restrict__ bhh,
    const float* __restrict__ coW, const float* __restrict__ cob,
    float* __restrict__ out,
    int B, int T, int LP)
{
    const int tid = threadIdx.x;

    // ---- stage weights as gate-pair ulonglong2, index (half*32+m)*32 + j ----
    for (int idx = tid; idx < 2048; idx += TB) {
        int hm = idx >> 5;          // half*32 + m
        int j  = idx & 31;
        int half = hm >> 5, m = hm & 31;
        const float* W = half ? Whh : Wih;
        ulonglong2 v;
        v.x = pack2(W[j * 32 + m],        W[(32 + j) * 32 + m]);
        v.y = pack2(W[(64 + j) * 32 + m], W[(96 + j) * 32 + m]);
        reinterpret_cast<ulonglong2*>(s_raw + OFF_W)[idx] = v;
    }
    if (tid < 32) {
        int j = tid;
        ulonglong2 b;
        b.x = pack2(bih[j] + bhh[j],           bih[32 + j] + bhh[32 + j]);
        b.y = pack2(bih[64 + j] + bhh[64 + j], bih[96 + j] + bhh[96 + j]);
        reinterpret_cast<ulonglong2*>(s_raw + OFF_B)[j] = b;
        reinterpret_cast<float4*>(s_raw + OFF_CO)[j] = make_float4(
            coW[j], coW[32 + j], coW[64 + j], coW[96 + j]);
#pragma unroll
        for (int k = 0; k < 6; k++) s_raw[OFF_CF + j * 8 + k] = cfW[j * 6 + k];
        s_raw[OFF_CF + j * 8 + 6] = cfb[j];
        s_raw[OFF_CF + j * 8 + 7] = 0.0f;
    }
    if (tid < 4) s_raw[OFF_COB + tid] = cob[tid];

    const int warpid = tid >> 5;
    const int pair = warpid >> 1;        // 0..1 within block
    const int w    = warpid & 1;         // gate half
    const int lane = tid & 31;

    // zero h read-buffer (buf 0) for my pair
#pragma unroll
    for (int jj = 0; jj < 16; jj++)
        s_raw[OFF_H + pair * 2048 + (w * 16 + jj) * 32 + lane] = 0.0f;
    __syncthreads();

    int rbase = pair * 2048;             // read buffer base (floats, rel OFF_H)
    int wbase = rbase + 1024;            // write buffer base

    const int e_raw = (blockIdx.x * 2 + pair) * 32 + lane;
    const bool valid = e_raw < B;
    const int e = valid ? e_raw : (B - 1);

    const float dt = 0.2f, hd2 = 0.02f;
    const float g0 = (float)(0.2 * 0.2 * 0.2 / 6.0);
    const float g1 = 0.02f;
    const float g2 = 0.2f;

    float tg[6];
#pragma unroll
    for (int i = 0; i < 6; i++) tg[i] = tanhf(p_coefG[i]);
    const float jk0 = p_jerk[0], jk1 = p_jerk[1];
    const float Ghx0 = g0 * tg[0] * jk0, Ghx1 = g1 * tg[1] * jk0, Ghx2 = g2 * tg[2] * jk0;
    const float Ghy0 = g0 * tg[3] * jk1, Ghy1 = g1 * tg[4] * jk1, Ghy2 = g2 * tg[5] * jk1;
    const float gt0 = g0 * tg[0], gt1 = g1 * tg[1], gt2 = g2 * tg[2];
    const float gt3 = g0 * tg[3], gt4 = g1 * tg[4], gt5 = g2 * tg[5];
    const float gr0 = p_GR[0], gr1 = p_GR[1];
    const float R00 = gr0 * gr0, R01 = gr0 * gr1, R11 = gr1 * gr1;

    const float2* hist2 = reinterpret_cast<const float2*>(hist);

    // ---- Kalman init (replicated in both warps of the pair) ----
    float2 z0 = hist2[e];
    float2 z1 = hist2[(size_t)B + e];
    float X[6];
    X[0] = z0.x; X[1] = (z1.x - z0.x) / dt; X[2] = 0.0f;
    X[3] = (z1.y - z0.y) / dt; X[4] = 0.0f; X[5] = 0.0f;

    float P[6][6];
#pragma unroll
    for (int i = 0; i < 6; i++)
#pragma unroll
        for (int j = 0; j < 6; j++) P[i][j] = 0.0f;
    {
        float d0 = p_psx[0], d1 = p_vsx[0], d2 = p_asx[0];
        float d3 = p_psy[0], d4 = p_vsy[0], d5 = p_asy[0];
        P[0][0] = d0 * d0; P[1][1] = d1 * d1; P[2][2] = d2 * d2;
        P[3][3] = d3 * d3; P[4][4] = d4 * d4; P[5][5] = d5 * d5;
    }

    float c[16];
#pragma unroll
    for (int jj = 0; jj < 16; jj++) c[jj] = 0.0f;

    // ================= history filtering =================
#pragma unroll 1
    for (int t = 1; t < T; t++) {
        lstm_step(w, lane, rbase, wbase, X, c);
        PAIR_SYNC(pair);
        int tmp = rbase; rbase = wbase; wbase = tmp;

        // X = F X
        {
            float x0 = X[0] + dt * X[1] + hd2 * X[2];
            float x1 = X[1] + dt * X[2];
            float x3 = X[3] + dt * X[4] + hd2 * X[5];
            float x4 = X[4] + dt * X[5];
            X[0] = x0; X[1] = x1; X[3] = x3; X[4] = x4;
        }
        // P = F P F^T + Q_hist
#pragma unroll
        for (int cc = 0; cc < 6; cc++) {
            P[0][cc] += dt * P[1][cc] + hd2 * P[2][cc];
            P[1][cc] += dt * P[2][cc];
            P[3][cc] += dt * P[4][cc] + hd2 * P[5][cc];
            P[4][cc] += dt * P[5][cc];
        }
#pragma unroll
        for (int r = 0; r < 6; r++) {
            P[r][0] += dt * P[r][1] + hd2 * P[r][2];
            P[r][1] += dt * P[r][2];
            P[r][3] += dt * P[r][4] + hd2 * P[r][5];
            P[r][4] += dt * P[r][5];
        }
        {
            float gx[3] = {Ghx0, Ghx1, Ghx2}, gy[3] = {Ghy0, Ghy1, Ghy2};
#pragma unroll
            for (int a = 0; a < 3; a++)
#pragma unroll
                for (int bb = 0; bb < 3; bb++) {
                    P[a][bb]         += gx[a] * gx[bb];
                    P[3 + a][3 + bb] += gy[a] * gy[bb];
                }
        }
        // measurement update
        float2 z = hist2[(size_t)t * B + e];
        float yx = z.x - X[0], yy = z.y - X[3];
        float S00 = P[0][0] + R00, S01 = P[0][3] + R01;
        float S10 = P[3][0] + R01, S11 = P[3][3] + R11;
        float rdet = 1.0f / (S00 * S11 - S01 * S10);
        float si00 =  S11 * rdet, si01 = -S01 * rdet;
        float si10 = -S10 * rdet, si11 =  S00 * rdet;
        float K0[6], K1[6];
#pragma unroll
        for (int i = 0; i < 6; i++) {
            K0[i] = P[i][0] * si00 + P[i][3] * si10;
            K1[i] = P[i][0] * si01 + P[i][3] * si11;
        }
#pragma unroll
        for (int i = 0; i < 6; i++) X[i] += K0[i] * yx + K1[i] * yy;
        // short-form covariance update: P = (I - K H) P
        float r0[6], r3[6];
#pragma unroll
        for (int j = 0; j < 6; j++) { r0[j] = P[0][j]; r3[j] = P[3][j]; }
#pragma unroll
        for (int i = 0; i < 6; i++)
#pragma unroll
            for (int j = 0; j < 6; j++) P[i][j] -= K0[i] * r0[j] + K1[i] * r3[j];
    }

    // ================= prediction =================
#pragma unroll 1
    for (int t = 0; t < LP; t++) {
        lstm_step(w, lane, rbase, wbase, X, c);
        PAIR_SYNC(pair);

        // command = coW @ h_new + cob, read from just-written buffer
        float cm0 = s_raw[OFF_COB + 0], cm1 = s_raw[OFF_COB + 1];
        float cm2 = s_raw[OFF_COB + 2], cm3 = s_raw[OFF_COB + 3];
        {
            const float* hb = s_raw + OFF_H + wbase + lane;
            const float4* co4 = reinterpret_cast<const float4*>(s_raw + OFF_CO);
#pragma unroll 2
            for (int m = 0; m < 32; m++) {
                float4 cw = co4[m];
                float hm = hb[m * 32];
                cm0 = fmaf(cw.x, hm, cm0);
                cm1 = fmaf(cw.y, hm, cm1);
                cm2 = fmaf(cw.z, hm, cm2);
                cm3 = fmaf(cw.w, hm, cm3);
            }
        }
        int tmp = rbase; rbase = wbase; wbase = tmp;

        // X = F X + B cmd[:2]
        {
            float x0 = X[0] + dt * X[1] + hd2 * X[2] + g0 * cm0;
            float x1 = X[1] + dt * X[2] + g1 * cm0;
            float x2 = X[2] + g2 * cm0;
            float x3 = X[3] + dt * X[4] + hd2 * X[5] + g0 * cm1;
            float x4 = X[4] + dt * X[5] + g1 * cm1;
            float x5 = X[5] + g2 * cm1;
            X[0] = x0; X[1] = x1; X[2] = x2; X[3] = x3; X[4] = x4; X[5] = x5;
        }
        float Gs[6] = {gt0 * cm2, gt1 * cm2, gt2 * cm2, gt3 * cm3, gt4 * cm3, gt5 * cm3};
        // P = F P F^T + Gs Gs^T
#pragma unroll
        for (int cc = 0; cc < 6; cc++) {
            P[0][cc] += dt * P[1][cc] + hd2 * P[2][cc];
            P[1][cc] += dt * P[2][cc];
            P[3][cc] += dt * P[4][cc] + hd2 * P[5][cc];
            P[4][cc] += dt * P[5][cc];
        }
#pragma unroll
        for (int r = 0; r < 6; r++) {
            P[r][0] += dt * P[r][1] + hd2 * P[r][2];
            P[r][1] += dt * P[r][2];
            P[r][3] += dt * P[r][4] + hd2 * P[r][5];
            P[r][4] += dt * P[r][5];
        }
#pragma unroll
        for (int i = 0; i < 6; i++)
#pragma unroll
            for (int j = 0; j < 6; j++) P[i][j] += Gs[i] * Gs[j];

        // outputs (warp half 0 writes; both halves hold identical X/P)
        if (valid && w == 0) {
            float sx = sqrtf(P[0][0]);
            float sy = sqrtf(P[3][3]);
            float rho = __fdividef(P[0][3] + P[3][0], 2.0f * sx * sy);
            size_t o = ((size_t)t * B + e) * 5;
            out[o + 0] = X[0];
            out[o + 1] = X[3];
            out[o + 2] = sx;
            out[o + 3] = sy;
            out[o + 4] = rho;
        }
    }
}

extern "C" void kernel_launch(void* const* d_in, const int* in_sizes, int n_in,
                              void* d_out, int out_size) {
    const float* hist  = (const float*)d_in[0];
    const float* psx   = (const float*)d_in[1];
    const float* psy   = (const float*)d_in[2];
    const float* vsx   = (const float*)d_in[3];
    const float* vsy   = (const float*)d_in[4];
    const float* asx   = (const float*)d_in[5];
    const float* asy   = (const float*)d_in[6];
    const float* jerk  = (const float*)d_in[7];
    const float* coefG = (const float*)d_in[8];
    const float* GR    = (const float*)d_in[9];
    const float* cfW   = (const float*)d_in[10];
    const float* cfb   = (const float*)d_in[11];
    const float* Wih   = (const float*)d_in[12];
    const float* Whh   = (const float*)d_in[13];
    const float* bih   = (const float*)d_in[14];
    const float* bhh   = (const float*)d_in[15];
    const float* coW   = (const float*)d_in[16];
    const float* cob   = (const float*)d_in[17];
    float* out = (float*)d_out;

    const int T = 16;
    int B  = in_sizes[0] / (2 * T);
    int LP = out_size / (B * 5);

    size_t smem = (size_t)SMEM_FLOATS * sizeof(float);  // 51264 bytes
    cudaFuncSetAttribute(kalman_lstm_kernel,
                         cudaFuncAttributeMaxDynamicSharedMemorySize, (int)smem);

    int groups = (B + 31) / 32;          // 32-element groups
    int grid = (groups + 1) / 2;         // 2 groups (pairs) per block
    kalman_lstm_kernel<<<grid, TB, smem>>>(
        hist, psx, psy, vsx, vsy, asx, asy, jerk, coefG, GR,
        cfW, cfb, Wih, Whh, bih, bhh, coW, cob, out, B, T, LP);
}

// round 7
// speedup vs baseline: 2.9211x; 1.0655x over previous
#include <cuda_runtime.h>

#define TB 128
typedef unsigned long long ull;

// fast sigmoid / tanh via MUFU; rel err ~1e-6; clamp-free (inf/0 limits correct).
__device__ __forceinline__ float fsig(float x) {
    float e = __expf(-x);
    return __fdividef(1.0f, 1.0f + e);
}
__device__ __forceinline__ float ftanh(float x) {
    float e = __expf(2.0f * x);
    return 1.0f - __fdividef(2.0f, e + 1.0f);
}
__device__ __forceinline__ ull pack2(float lo, float hi) {
    ull r; asm("mov.b64 %0, {%1, %2};" : "=l"(r) : "f"(lo), "f"(hi)); return r;
}
__device__ __forceinline__ ull dup2(float v) {
    ull r; asm("mov.b64 %0, {%1, %1};" : "=l"(r) : "f"(v)); return r;
}
__device__ __forceinline__ void unpack2(ull v, float& lo, float& hi) {
    asm("mov.b64 {%0, %1}, %2;" : "=f"(lo), "=f"(hi) : "l"(v));
}
#define FMA2(acc, w, a) asm("fma.rn.f32x2 %0, %1, %2, %0;" : "+l"(acc) : "l"(w), "l"(a))

// per-pair barrier (64 threads), ids 1 and 2
#define PAIR_SYNC(p) asm volatile("bar.sync %0, 64;" :: "r"((p) + 1) : "memory")

// float-unit offsets in dynamic smem
#define OFF_W   0      // ulonglong2[2048]: gate-pair weights [(half*32+m)*32 + j]
#define OFF_B   8192   // ulonglong2[32]  : bias pairs per j
#define OFF_CO  8320   // float4[32]      : coW columns per m
#define OFF_CF  8448   // float[32*8]     : cf rows (6w + b + pad)
#define OFF_COB 8704   // float[4]
#define OFF_K   8708   // float[16]      : runtime Kalman consts
#define OFF_H   8736   // float[2 pair][32 m][32 lane]  (single buffer)
#define OFF_F   10784  // float[2 pair][32 m][32 lane]  (feat buffer)
#define SMEM_FLOATS 12832

// Kalman const indices in OFF_K
#define KC_GHX 0   // 0..2
#define KC_GHY 3   // 3..5
#define KC_R   6   // R00, R01, R11
#define KC_GT  9   // 9..14

extern __shared__ float s_raw[];

// One LSTM step; warp (half w of pair) computes gates j = w*16 .. w*16+15.
// feat split across the pair (each computes 16 m), exchanged via smem.
// Two accumulator passes of 8 gates keep register pressure low.
// Internally: feat -> sync -> passes -> sync -> h write.
__device__ __forceinline__ void lstm_step(
    int pair, int w, int lane,
    const float* __restrict__ X, float* __restrict__ c)
{
    // 1. my 16 feat values (m = w*16 + k) -> smem
    {
        const float4* cf = reinterpret_cast<const float4*>(s_raw + OFF_CF) + w * 32;
        float* fout = s_raw + OFF_F + pair * 1024 + (w * 16) * 32 + lane;
#pragma unroll 2
        for (int k = 0; k < 16; k++) {
            float4 a = cf[0];
            float4 b = cf[1];
            cf += 2;
            float acc = b.z;
            acc = fmaf(a.x, X[0], acc);
            acc = fmaf(a.y, X[1], acc);
            acc = fmaf(a.z, X[2], acc);
            acc = fmaf(a.w, X[3], acc);
            acc = fmaf(b.x, X[4], acc);
            acc = fmaf(b.y, X[5], acc);
            fout[k * 32] = ftanh(acc);
        }
    }
    PAIR_SYNC(pair);   // feat ready; also orders prev-step h writes before reads

    // 2. gate passes (8 gates each)
    float hnew[16];
    const float* fin = s_raw + OFF_F + pair * 1024 + lane;
    const float* hin = s_raw + OFF_H + pair * 1024 + lane;
#pragma unroll 1
    for (int pass = 0; pass < 2; pass++) {
        const int jb = w * 16 + pass * 8;
        ull acc_if[8], acc_go[8];
        {
            const ulonglong2* sb = reinterpret_cast<const ulonglong2*>(s_raw + OFF_B) + jb;
#pragma unroll
            for (int jj = 0; jj < 8; jj++) {
                ulonglong2 b = sb[jj];
                acc_if[jj] = b.x; acc_go[jj] = b.y;
            }
        }
        const ulonglong2* row = reinterpret_cast<const ulonglong2*>(s_raw + OFF_W) + jb;
#pragma unroll 2
        for (int m = 0; m < 32; m++) {
            ull a2 = dup2(fin[m * 32]);
#pragma unroll
            for (int jj = 0; jj < 8; jj++) {
                ulonglong2 ww = row[jj];
                FMA2(acc_if[jj], ww.x, a2);
                FMA2(acc_go[jj], ww.y, a2);
            }
            row += 32;
        }
#pragma unroll 2
        for (int m = 0; m < 32; m++) {
            ull a2 = dup2(hin[m * 32]);
#pragma unroll
            for (int jj = 0; jj < 8; jj++) {
                ulonglong2 ww = row[jj];
                FMA2(acc_if[jj], ww.x, a2);
                FMA2(acc_go[jj], ww.y, a2);
            }
            row += 32;
        }
        // nonlinearities for this pass
#pragma unroll
        for (int jj = 0; jj < 8; jj++) {
            float gi, gf, gg, go;
            unpack2(acc_if[jj], gi, gf);
            unpack2(acc_go[jj], gg, go);
            float ig = fsig(gi), fg = fsig(gf);
            float g_ = ftanh(gg), og = fsig(go);
            float cj = fmaf(fg, c[pass * 8 + jj], ig * g_);
            c[pass * 8 + jj] = cj;
            hnew[pass * 8 + jj] = og * ftanh(cj);
        }
    }
    PAIR_SYNC(pair);   // all h reads done

    // 3. write my 16 h values
    {
        float* hout = s_raw + OFF_H + pair * 1024 + (w * 16) * 32 + lane;
#pragma unroll
        for (int jj = 0; jj < 16; jj++) hout[jj * 32] = hnew[jj];
    }
}

__global__ void __launch_bounds__(TB, 4) kalman_lstm_kernel(
    const float* __restrict__ hist,
    const float* __restrict__ p_psx, const float* __restrict__ p_psy,
    const float* __restrict__ p_vsx, const float* __restrict__ p_vsy,
    const float* __restrict__ p_asx, const float* __restrict__ p_asy,
    const float* __restrict__ p_jerk, const float* __restrict__ p_coefG,
    const float* __restrict__ p_GR,
    const float* __restrict__ cfW, const float* __restrict__ cfb,
    const float* __restrict__ Wih, const float* __restrict__ Whh,
    const float* __restrict__ bih, const float* __restrict__ bhh,
    const float* __restrict__ coW, const float* __restrict__ cob,
    float* __restrict__ out,
    int B, int T, int LP)
{
    const int tid = threadIdx.x;

    // ---- stage weights as gate-pair ulonglong2 ----
    for (int idx = tid; idx < 2048; idx += TB) {
        int hm = idx >> 5;
        int j  = idx & 31;
        int half = hm >> 5, m = hm & 31;
        const float* W = half ? Whh : Wih;
        ulonglong2 v;
        v.x = pack2(W[j * 32 + m],        W[(32 + j) * 32 + m]);
        v.y = pack2(W[(64 + j) * 32 + m], W[(96 + j) * 32 + m]);
        reinterpret_cast<ulonglong2*>(s_raw + OFF_W)[idx] = v;
    }
    if (tid < 32) {
        int j = tid;
        ulonglong2 b;
        b.x = pack2(bih[j] + bhh[j],           bih[32 + j] + bhh[32 + j]);
        b.y = pack2(bih[64 + j] + bhh[64 + j], bih[96 + j] + bhh[96 + j]);
        reinterpret_cast<ulonglong2*>(s_raw + OFF_B)[j] = b;
        reinterpret_cast<float4*>(s_raw + OFF_CO)[j] = make_float4(
            coW[j], coW[32 + j], coW[64 + j], coW[96 + j]);
#pragma unroll
        for (int k = 0; k < 6; k++) s_raw[OFF_CF + j * 8 + k] = cfW[j * 6 + k];
        s_raw[OFF_CF + j * 8 + 6] = cfb[j];
        s_raw[OFF_CF + j * 8 + 7] = 0.0f;
    }
    if (tid < 4) s_raw[OFF_COB + tid] = cob[tid];
    if (tid == 0) {
        // runtime Kalman constants -> smem (kept out of registers)
        const float g0 = (float)(0.2 * 0.2 * 0.2 / 6.0), g1 = 0.02f, g2 = 0.2f;
        float tg0 = tanhf(p_coefG[0]), tg1 = tanhf(p_coefG[1]), tg2 = tanhf(p_coefG[2]);
        float tg3 = tanhf(p_coefG[3]), tg4 = tanhf(p_coefG[4]), tg5 = tanhf(p_coefG[5]);
        float jk0 = p_jerk[0], jk1 = p_jerk[1];
        s_raw[OFF_K + KC_GHX + 0] = g0 * tg0 * jk0;
        s_raw[OFF_K + KC_GHX + 1] = g1 * tg1 * jk0;
        s_raw[OFF_K + KC_GHX + 2] = g2 * tg2 * jk0;
        s_raw[OFF_K + KC_GHY + 0] = g0 * tg3 * jk1;
        s_raw[OFF_K + KC_GHY + 1] = g1 * tg4 * jk1;
        s_raw[OFF_K + KC_GHY + 2] = g2 * tg5 * jk1;
        float gr0 = p_GR[0], gr1 = p_GR[1];
        s_raw[OFF_K + KC_R + 0] = gr0 * gr0;
        s_raw[OFF_K + KC_R + 1] = gr0 * gr1;
        s_raw[OFF_K + KC_R + 2] = gr1 * gr1;
        s_raw[OFF_K + KC_GT + 0] = g0 * tg0;
        s_raw[OFF_K + KC_GT + 1] = g1 * tg1;
        s_raw[OFF_K + KC_GT + 2] = g2 * tg2;
        s_raw[OFF_K + KC_GT + 3] = g0 * tg3;
        s_raw[OFF_K + KC_GT + 4] = g1 * tg4;
        s_raw[OFF_K + KC_GT + 5] = g2 * tg5;
    }

    const int warpid = tid >> 5;
    const int pair = warpid >> 1;
    const int w    = warpid & 1;
    const int lane = tid & 31;

    // zero my 16 rows of the h buffer
#pragma unroll
    for (int jj = 0; jj < 16; jj++)
        s_raw[OFF_H + pair * 1024 + (w * 16 + jj) * 32 + lane] = 0.0f;
    __syncthreads();

    const int e_raw = (blockIdx.x * 2 + pair) * 32 + lane;
    const bool valid = e_raw < B;
    const int e = valid ? e_raw : (B - 1);

    const float dt = 0.2f, hd2 = 0.02f;
    const float g0 = (float)(0.2 * 0.2 * 0.2 / 6.0);
    const float g1 = 0.02f;
    const float g2 = 0.2f;

    const float2* hist2 = reinterpret_cast<const float2*>(hist);

    // ---- Kalman init (replicated in both warps of the pair) ----
    float2 z0 = hist2[e];
    float2 z1 = hist2[(size_t)B + e];
    float X[6];
    X[0] = z0.x; X[1] = (z1.x - z0.x) / dt; X[2] = 0.0f;
    X[3] = (z1.y - z0.y) / dt; X[4] = 0.0f; X[5] = 0.0f;

    float P[6][6];
#pragma unroll
    for (int i = 0; i < 6; i++)
#pragma unroll
        for (int j = 0; j < 6; j++) P[i][j] = 0.0f;
    {
        float d0 = p_psx[0], d1 = p_vsx[0], d2 = p_asx[0];
        float d3 = p_psy[0], d4 = p_vsy[0], d5 = p_asy[0];
        P[0][0] = d0 * d0; P[1][1] = d1 * d1; P[2][2] = d2 * d2;
        P[3][3] = d3 * d3; P[4][4] = d4 * d4; P[5][5] = d5 * d5;
    }

    float c[16];
#pragma unroll
    for (int jj = 0; jj < 16; jj++) c[jj] = 0.0f;

    const float* KC = s_raw + OFF_K;

    // ================= history filtering =================
#pragma unroll 1
    for (int t = 1; t < T; t++) {
        lstm_step(pair, w, lane, X, c);

        // X = F X
        {
            float x0 = X[0] + dt * X[1] + hd2 * X[2];
            float x1 = X[1] + dt * X[2];
            float x3 = X[3] + dt * X[4] + hd2 * X[5];
            float x4 = X[4] + dt * X[5];
            X[0] = x0; X[1] = x1; X[3] = x3; X[4] = x4;
        }
        // P = F P F^T + Q_hist
#pragma unroll
        for (int cc = 0; cc < 6; cc++) {
            P[0][cc] += dt * P[1][cc] + hd2 * P[2][cc];
            P[1][cc] += dt * P[2][cc];
            P[3][cc] += dt * P[4][cc] + hd2 * P[5][cc];
            P[4][cc] += dt * P[5][cc];
        }
#pragma unroll
        for (int r = 0; r < 6; r++) {
            P[r][0] += dt * P[r][1] + hd2 * P[r][2];
            P[r][1] += dt * P[r][2];
            P[r][3] += dt * P[r][4] + hd2 * P[r][5];
            P[r][4] += dt * P[r][5];
        }
        {
            float gx0 = KC[KC_GHX], gx1 = KC[KC_GHX + 1], gx2 = KC[KC_GHX + 2];
            float gy0 = KC[KC_GHY], gy1 = KC[KC_GHY + 1], gy2 = KC[KC_GHY + 2];
            float gx[3] = {gx0, gx1, gx2}, gy[3] = {gy0, gy1, gy2};
#pragma unroll
            for (int a = 0; a < 3; a++)
#pragma unroll
                for (int bb = 0; bb < 3; bb++) {
                    P[a][bb]         += gx[a] * gx[bb];
                    P[3 + a][3 + bb] += gy[a] * gy[bb];
                }
        }
        // measurement update
        float R00 = KC[KC_R], R01 = KC[KC_R + 1], R11 = KC[KC_R + 2];
        float2 z = hist2[(size_t)t * B + e];
        float yx = z.x - X[0], yy = z.y - X[3];
        float S00 = P[0][0] + R00, S01 = P[0][3] + R01;
        float S10 = P[3][0] + R01, S11 = P[3][3] + R11;
        float rdet = 1.0f / (S00 * S11 - S01 * S10);
        float si00 =  S11 * rdet, si01 = -S01 * rdet;
        float si10 = -S10 * rdet, si11 =  S00 * rdet;
        float K0[6], K1[6];
#pragma unroll
        for (int i = 0; i < 6; i++) {
            K0[i] = P[i][0] * si00 + P[i][3] * si10;
            K1[i] = P[i][0] * si01 + P[i][3] * si11;
        }
#pragma unroll
        for (int i = 0; i < 6; i++) X[i] += K0[i] * yx + K1[i] * yy;
        // short-form covariance update: P = (I - K H) P
        float r0[6], r3[6];
#pragma unroll
        for (int j = 0; j < 6; j++) { r0[j] = P[0][j]; r3[j] = P[3][j]; }
#pragma unroll
        for (int i = 0; i < 6; i++)
#pragma unroll
            for (int j = 0; j < 6; j++) P[i][j] -= K0[i] * r0[j] + K1[i] * r3[j];
    }

    // ================= prediction =================
#pragma unroll 1
    for (int t = 0; t < LP; t++) {
        lstm_step(pair, w, lane, X, c);
        PAIR_SYNC(pair);   // h fully written before command reduction

        // command = coW @ h_new + cob
        float cm0 = s_raw[OFF_COB + 0], cm1 = s_raw[OFF_COB + 1];
        float cm2 = s_raw[OFF_COB + 2], cm3 = s_raw[OFF_COB + 3];
        {
            const float* hb = s_raw + OFF_H + pair * 1024 + lane;
            const float4* co4 = reinterpret_cast<const float4*>(s_raw + OFF_CO);
#pragma unroll 2
            for (int m = 0; m < 32; m++) {
                float4 cw = co4[m];
                float hm = hb[m * 32];
                cm0 = fmaf(cw.x, hm, cm0);
                cm1 = fmaf(cw.y, hm, cm1);
                cm2 = fmaf(cw.z, hm, cm2);
                cm3 = fmaf(cw.w, hm, cm3);
            }
        }

        // X = F X + B cmd[:2]
        {
            float x0 = X[0] + dt * X[1] + hd2 * X[2] + g0 * cm0;
            float x1 = X[1] + dt * X[2] + g1 * cm0;
            float x2 = X[2] + g2 * cm0;
            float x3 = X[3] + dt * X[4] + hd2 * X[5] + g0 * cm1;
            float x4 = X[4] + dt * X[5] + g1 * cm1;
            float x5 = X[5] + g2 * cm1;
            X[0] = x0; X[1] = x1; X[2] = x2; X[3] = x3; X[4] = x4; X[5] = x5;
        }
        float Gs[6];
        {
            Gs[0] = KC[KC_GT + 0] * cm2;
            Gs[1] = KC[KC_GT + 1] * cm2;
            Gs[2] = KC[KC_GT + 2] * cm2;
            Gs[3] = KC[KC_GT + 3] * cm3;
            Gs[4] = KC[KC_GT + 4] * cm3;
            Gs[5] = KC[KC_GT + 5] * cm3;
        }
        // P = F P F^T + Gs Gs^T
#pragma unroll
        for (int cc = 0; cc < 6; cc++) {
            P[0][cc] += dt * P[1][cc] + hd2 * P[2][cc];
            P[1][cc] += dt * P[2][cc];
            P[3][cc] += dt * P[4][cc] + hd2 * P[5][cc];
            P[4][cc] += dt * P[5][cc];
        }
#pragma unroll
        for (int r = 0; r < 6; r++) {
            P[r][0] += dt * P[r][1] + hd2 * P[r][2];
            P[r][1] += dt * P[r][2];
            P[r][3] += dt * P[r][4] + hd2 * P[r][5];
            P[r][4] += dt * P[r][5];
        }
#pragma unroll
        for (int i = 0; i < 6; i++)
#pragma unroll
            for (int j = 0; j < 6; j++) P[i][j] += Gs[i] * Gs[j];

        // outputs (warp half 0 writes; both halves hold identical X/P)
        if (valid && w == 0) {
            float sx = sqrtf(P[0][0]);
            float sy = sqrtf(P[3][3]);
            float rho = __fdividef(P[0][3] + P[3][0], 2.0f * sx * sy);
            size_t o = ((size_t)t * B + e) * 5;
            out[o + 0] = X[0];
            out[o + 1] = X[3];
            out[o + 2] = sx;
            out[o + 3] = sy;
            out[o + 4] = rho;
        }
    }
}

extern "C" void kernel_launch(void* const* d_in, const int* in_sizes, int n_in,
                              void* d_out, int out_size) {
    const float* hist  = (const float*)d_in[0];
    const float* psx   = (const float*)d_in[1];
    const float* psy   = (const float*)d_in[2];
    const float* vsx   = (const float*)d_in[3];
    const float* vsy   = (const float*)d_in[4];
    const float* asx   = (const float*)d_in[5];
    const float* asy   = (const float*)d_in[6];
    const float* jerk  = (const float*)d_in[7];
    const float* coefG = (const float*)d_in[8];
    const float* GR    = (const float*)d_in[9];
    const float* cfW   = (const float*)d_in[10];
    const float* cfb   = (const float*)d_in[11];
    const float* Wih   = (const float*)d_in[12];
    const float* Whh   = (const float*)d_in[13];
    const float* bih   = (const float*)d_in[14];
    const float* bhh   = (const float*)d_in[15];
    const float* coW   = (const float*)d_in[16];
    const float* cob   = (const float*)d_in[17];
    float* out = (float*)d_out;

    const int T = 16;
    int B  = in_sizes[0] / (2 * T);
    int LP = out_size / (B * 5);

    size_t smem = (size_t)SMEM_FLOATS * sizeof(float);  // 51328 bytes
    cudaFuncSetAttribute(kalman_lstm_kernel,
                         cudaFuncAttributeMaxDynamicSharedMemorySize, (int)smem);

    int groups = (B + 31) / 32;
    int grid = (groups + 1) / 2;
    kalman_lstm_kernel<<<grid, TB, smem>>>(
        hist, psx, psy, vsx, vsy, asx, asy, jerk, coefG, GR,
        cfW, cfb, Wih, Whh, bih, bhh, coW, cob, out, B, T, LP);
}

// round 8
// speedup vs baseline: 3.6056x; 1.2343x over previous
#include <cuda_runtime.h>

#define TB 256
typedef unsigned long long ull;

__device__ __forceinline__ float fsig(float x) {
    float e = __expf(-x);
    return __fdividef(1.0f, 1.0f + e);
}
__device__ __forceinline__ float ftanh(float x) {
    float e = __expf(2.0f * x);
    return 1.0f - __fdividef(2.0f, e + 1.0f);
}
__device__ __forceinline__ ull pack2(float lo, float hi) {
    ull r; asm("mov.b64 %0, {%1, %2};" : "=l"(r) : "f"(lo), "f"(hi)); return r;
}
__device__ __forceinline__ ull dup2(float v) {
    ull r; asm("mov.b64 %0, {%1, %1};" : "=l"(r) : "f"(v)); return r;
}
__device__ __forceinline__ void unpack2(ull v, float& lo, float& hi) {
    asm("mov.b64 {%0, %1}, %2;" : "=f"(lo), "=f"(hi) : "l"(v));
}
#define FMA2(acc, w, a) asm("fma.rn.f32x2 %0, %1, %2, %0;" : "+l"(acc) : "l"(w), "l"(a))

// named barriers: pair of LSTM warps (64 thr), whole group (128 thr)
#define PAIRBAR(g)  asm volatile("bar.sync %0, 64;"  :: "r"((g) + 1) : "memory")
#define GROUPBAR(g) asm volatile("bar.sync %0, 128;" :: "r"((g) + 3) : "memory")

// smem float offsets
#define OFF_W   0      // ull2[2048] gate-pair weights [m_global*32 + j], m_global 0..63
#define OFF_B   8192   // ull2[32] bias pairs
#define OFF_CO  8320   // float4[32] coW
#define OFF_CF  8448   // float[32*8] cf rows
#define OFF_COB 8704
#define OFF_K   8708   // 16 runtime Kalman consts
#define OFF_GRP 8736
#define GRP_FLOATS 7168
#define GX    0        // [2 buf][8 k][64 el]
#define GFEAT 1024     // [32 m][64 el]
#define GH    3072     // [32 j][64 el]
#define GC    5120     // [32 j][64 el]
#define SMEM_FLOATS (8736 + 2 * 7168)

#define KC_GHX 0
#define KC_GHY 3
#define KC_R   6
#define KC_GT  9

extern __shared__ float s_raw[];

__global__ void __launch_bounds__(TB, 2) kalman_lstm_kernel(
    const float* __restrict__ hist,
    const float* __restrict__ p_psx, const float* __restrict__ p_psy,
    const float* __restrict__ p_vsx, const float* __restrict__ p_vsy,
    const float* __restrict__ p_asx, const float* __restrict__ p_asy,
    const float* __restrict__ p_jerk, const float* __restrict__ p_coefG,
    const float* __restrict__ p_GR,
    const float* __restrict__ cfW, const float* __restrict__ cfb,
    const float* __restrict__ Wih, const float* __restrict__ Whh,
    const float* __restrict__ bih, const float* __restrict__ bhh,
    const float* __restrict__ coW, const float* __restrict__ cob,
    float* __restrict__ out,
    int B, int LP)
{
    const int tid = threadIdx.x;
    const int warpid = tid >> 5;
    const int lane = tid & 31;

    // ---- stage weights/consts (all 256 threads) ----
    for (int idx = tid; idx < 2048; idx += TB) {
        int mg = idx >> 5;             // 0..63
        int j  = idx & 31;
        const float* W = (mg < 32) ? Wih : Whh;
        int m = mg & 31;
        ulonglong2 v;
        v.x = pack2(W[j * 32 + m],        W[(32 + j) * 32 + m]);
        v.y = pack2(W[(64 + j) * 32 + m], W[(96 + j) * 32 + m]);
        reinterpret_cast<ulonglong2*>(s_raw + OFF_W)[idx] = v;
    }
    if (tid < 32) {
        int j = tid;
        ulonglong2 b;
        b.x = pack2(bih[j] + bhh[j],           bih[32 + j] + bhh[32 + j]);
        b.y = pack2(bih[64 + j] + bhh[64 + j], bih[96 + j] + bhh[96 + j]);
        reinterpret_cast<ulonglong2*>(s_raw + OFF_B)[j] = b;
        reinterpret_cast<float4*>(s_raw + OFF_CO)[j] = make_float4(
            coW[j], coW[32 + j], coW[64 + j], coW[96 + j]);
#pragma unroll
        for (int k = 0; k < 6; k++) s_raw[OFF_CF + j * 8 + k] = cfW[j * 6 + k];
        s_raw[OFF_CF + j * 8 + 6] = cfb[j];
        s_raw[OFF_CF + j * 8 + 7] = 0.0f;
    }
    if (tid == 32) {
        const float g0 = (float)(0.2 * 0.2 * 0.2 / 6.0), g1 = 0.02f, g2 = 0.2f;
        float tg0 = tanhf(p_coefG[0]), tg1 = tanhf(p_coefG[1]), tg2 = tanhf(p_coefG[2]);
        float tg3 = tanhf(p_coefG[3]), tg4 = tanhf(p_coefG[4]), tg5 = tanhf(p_coefG[5]);
        float jk0 = p_jerk[0], jk1 = p_jerk[1];
        s_raw[OFF_K + KC_GHX + 0] = g0 * tg0 * jk0;
        s_raw[OFF_K + KC_GHX + 1] = g1 * tg1 * jk0;
        s_raw[OFF_K + KC_GHX + 2] = g2 * tg2 * jk0;
        s_raw[OFF_K + KC_GHY + 0] = g0 * tg3 * jk1;
        s_raw[OFF_K + KC_GHY + 1] = g1 * tg4 * jk1;
        s_raw[OFF_K + KC_GHY + 2] = g2 * tg5 * jk1;
        float gr0 = p_GR[0], gr1 = p_GR[1];
        s_raw[OFF_K + KC_R + 0] = gr0 * gr0;
        s_raw[OFF_K + KC_R + 1] = gr0 * gr1;
        s_raw[OFF_K + KC_R + 2] = gr1 * gr1;
        s_raw[OFF_K + KC_GT + 0] = g0 * tg0;
        s_raw[OFF_K + KC_GT + 1] = g1 * tg1;
        s_raw[OFF_K + KC_GT + 2] = g2 * tg2;
        s_raw[OFF_K + KC_GT + 3] = g0 * tg3;
        s_raw[OFF_K + KC_GT + 4] = g1 * tg4;
        s_raw[OFF_K + KC_GT + 5] = g2 * tg5;
        s_raw[OFF_COB + 0] = cob[0]; s_raw[OFF_COB + 1] = cob[1];
        s_raw[OFF_COB + 2] = cob[2]; s_raw[OFF_COB + 3] = cob[3];
    }

    const float dt = 0.2f, hd2 = 0.02f;
    const float g0 = (float)(0.2 * 0.2 * 0.2 / 6.0);
    const float g1 = 0.02f;
    const float g2 = 0.2f;
    const float2* hist2 = reinterpret_cast<const float2*>(hist);

    // Kalman persistent state (live only on Kalman warps)
    float X[6], P[6][6];
    int e = 0; bool valid = false;

    if (warpid < 4) {
        // LSTM warp init: zero my 16 rows of H and C
        const int g = warpid >> 1, w = warpid & 1;
        float* base = s_raw + OFF_GRP + g * GRP_FLOATS;
#pragma unroll
        for (int jj = 0; jj < 16; jj++) {
            int j = w * 16 + jj;
            base[GH + j * 64 + lane] = 0.0f;
            base[GH + j * 64 + 32 + lane] = 0.0f;
            base[GC + j * 64 + lane] = 0.0f;
            base[GC + j * 64 + 32 + lane] = 0.0f;
        }
    } else {
        // Kalman warp init
        const int g = (warpid - 4) >> 1, half = (warpid - 4) & 1;
        const int el = half * 32 + lane;
        int e_raw = blockIdx.x * 128 + g * 64 + el;
        valid = e_raw < B;
        e = valid ? e_raw : (B - 1);
        float2 z0 = hist2[e];
        float2 z1 = hist2[(size_t)B + e];
        X[0] = z0.x; X[1] = (z1.x - z0.x) / dt; X[2] = 0.0f;
        X[3] = (z1.y - z0.y) / dt; X[4] = 0.0f; X[5] = 0.0f;
#pragma unroll
        for (int i = 0; i < 6; i++)
#pragma unroll
            for (int j = 0; j < 6; j++) P[i][j] = 0.0f;
        float d0 = p_psx[0], d1 = p_vsx[0], d2 = p_asx[0];
        float d3 = p_psy[0], d4 = p_vsy[0], d5 = p_asy[0];
        P[0][0] = d0 * d0; P[1][1] = d1 * d1; P[2][2] = d2 * d2;
        P[3][3] = d3 * d3; P[4][4] = d4 * d4; P[5][5] = d5 * d5;
        // publish X0 to buffer 0
        float* xw = s_raw + OFF_GRP + g * GRP_FLOATS + GX;
#pragma unroll
        for (int k = 0; k < 6; k++) xw[k * 64 + el] = X[k];
    }
    __syncthreads();

    if (warpid < 4) {
        // ======================= LSTM warps =======================
        const int g = warpid >> 1, w = warpid & 1;
        float* base = s_raw + OFF_GRP + g * GRP_FLOATS;
        float* FEAT = base + GFEAT;
        float* H    = base + GH;
        float* C    = base + GC;
        const int eA = lane, eB = lane + 32;
        int xb = 0;
        const int TS = 15 + LP;

#pragma unroll 1
        for (int step = 0; step < TS; step++) {
            // ---- feat for my 16 m rows, both elements ----
            {
                const float* xp = base + GX + xb * 512;
                float XA[6], XBv[6];
#pragma unroll
                for (int k = 0; k < 6; k++) {
                    XA[k]  = xp[k * 64 + eA];
                    XBv[k] = xp[k * 64 + eB];
                }
                const float4* cf = reinterpret_cast<const float4*>(s_raw + OFF_CF) + w * 32;
#pragma unroll 2
                for (int k = 0; k < 16; k++) {
                    int m = w * 16 + k;
                    float4 a = cf[0];
                    float4 b = cf[1];
                    cf += 2;
                    float accA = b.z, accB = b.z;
                    accA = fmaf(a.x, XA[0], accA);  accB = fmaf(a.x, XBv[0], accB);
                    accA = fmaf(a.y, XA[1], accA);  accB = fmaf(a.y, XBv[1], accB);
                    accA = fmaf(a.z, XA[2], accA);  accB = fmaf(a.z, XBv[2], accB);
                    accA = fmaf(a.w, XA[3], accA);  accB = fmaf(a.w, XBv[3], accB);
                    accA = fmaf(b.x, XA[4], accA);  accB = fmaf(b.x, XBv[4], accB);
                    accA = fmaf(b.y, XA[5], accA);  accB = fmaf(b.y, XBv[5], accB);
                    FEAT[m * 64 + eA] = ftanh(accA);
                    FEAT[m * 64 + eB] = ftanh(accB);
                }
            }
            PAIRBAR(g);   // feat complete (and prior-step H writes visible)

            // ---- gate passes: 2 passes x 8 j, 2 elements per lane ----
            float hA[16], hB[16];
#pragma unroll 1
            for (int pass = 0; pass < 2; pass++) {
                const int jb = w * 16 + pass * 8;
                ull aifA[8], agoA[8], aifB[8], agoB[8];
                {
                    const ulonglong2* sb = reinterpret_cast<const ulonglong2*>(s_raw + OFF_B) + jb;
#pragma unroll
                    for (int jj = 0; jj < 8; jj++) {
                        ulonglong2 b = sb[jj];
                        aifA[jj] = b.x; agoA[jj] = b.y;
                        aifB[jj] = b.x; agoB[jj] = b.y;
                    }
                }
                const ulonglong2* row = reinterpret_cast<const ulonglong2*>(s_raw + OFF_W) + jb;
                const float* fA = FEAT + eA;
                const float* fB = FEAT + eB;
#pragma unroll 2
                for (int m = 0; m < 32; m++) {
                    ull a2A = dup2(fA[m * 64]);
                    ull a2B = dup2(fB[m * 64]);
#pragma unroll
                    for (int jj = 0; jj < 8; jj++) {
                        ulonglong2 ww = row[jj];
                        FMA2(aifA[jj], ww.x, a2A);
                        FMA2(agoA[jj], ww.y, a2A);
                        FMA2(aifB[jj], ww.x, a2B);
                        FMA2(agoB[jj], ww.y, a2B);
                    }
                    row += 32;
                }
                const float* hIA = H + eA;
                const float* hIB = H + eB;
#pragma unroll 2
                for (int m = 0; m < 32; m++) {
                    ull a2A = dup2(hIA[m * 64]);
                    ull a2B = dup2(hIB[m * 64]);
#pragma unroll
                    for (int jj = 0; jj < 8; jj++) {
                        ulonglong2 ww = row[jj];
                        FMA2(aifA[jj], ww.x, a2A);
                        FMA2(agoA[jj], ww.y, a2A);
                        FMA2(aifB[jj], ww.x, a2B);
                        FMA2(agoB[jj], ww.y, a2B);
                    }
                    row += 32;
                }
                // nonlinearities + c update (c in smem)
#pragma unroll
                for (int jj = 0; jj < 8; jj++) {
                    int j = jb + jj;
                    float gi, gf, gg, go;
                    unpack2(aifA[jj], gi, gf);
                    unpack2(agoA[jj], gg, go);
                    float ig = fsig(gi), fg = fsig(gf);
                    float g_ = ftanh(gg), og = fsig(go);
                    float cj = fmaf(fg, C[j * 64 + eA], ig * g_);
                    C[j * 64 + eA] = cj;
                    hA[pass * 8 + jj] = og * ftanh(cj);

                    unpack2(aifB[jj], gi, gf);
                    unpack2(agoB[jj], gg, go);
                    ig = fsig(gi); fg = fsig(gf);
                    g_ = ftanh(gg); og = fsig(go);
                    cj = fmaf(fg, C[j * 64 + eB], ig * g_);
                    C[j * 64 + eB] = cj;
                    hB[pass * 8 + jj] = og * ftanh(cj);
                }
            }
            PAIRBAR(g);   // all H reads (both warps) done

            // ---- write h ----
#pragma unroll
            for (int jj = 0; jj < 16; jj++) {
                int j = w * 16 + jj;
                H[j * 64 + eA] = hA[jj];
                H[j * 64 + eB] = hB[jj];
            }

            GROUPBAR(g);                 // hist: X(t) ready / pred: barA (h ready)
            if (step >= 15) GROUPBAR(g); // pred: barB (X(t) ready)
            xb ^= 1;
        }
    } else {
        // ======================= Kalman warps =======================
        const int g = (warpid - 4) >> 1, half = (warpid - 4) & 1;
        const int el = half * 32 + lane;
        float* base = s_raw + OFF_GRP + g * GRP_FLOATS;
        const float* KC = s_raw + OFF_K;
        int xb = 0;

        // ---------- history t = 1..15 ----------
#pragma unroll 1
        for (int t = 1; t < 16; t++) {
            // predict
            {
                float x0 = X[0] + dt * X[1] + hd2 * X[2];
                float x1 = X[1] + dt * X[2];
                float x3 = X[3] + dt * X[4] + hd2 * X[5];
                float x4 = X[4] + dt * X[5];
                X[0] = x0; X[1] = x1; X[3] = x3; X[4] = x4;
            }
#pragma unroll
            for (int cc = 0; cc < 6; cc++) {
                P[0][cc] += dt * P[1][cc] + hd2 * P[2][cc];
                P[1][cc] += dt * P[2][cc];
                P[3][cc] += dt * P[4][cc] + hd2 * P[5][cc];
                P[4][cc] += dt * P[5][cc];
            }
#pragma unroll
            for (int r = 0; r < 6; r++) {
                P[r][0] += dt * P[r][1] + hd2 * P[r][2];
                P[r][1] += dt * P[r][2];
                P[r][3] += dt * P[r][4] + hd2 * P[r][5];
                P[r][4] += dt * P[r][5];
            }
            {
                float gx[3] = {KC[KC_GHX], KC[KC_GHX + 1], KC[KC_GHX + 2]};
                float gy[3] = {KC[KC_GHY], KC[KC_GHY + 1], KC[KC_GHY + 2]};
#pragma unroll
                for (int a = 0; a < 3; a++)
#pragma unroll
                    for (int bb = 0; bb < 3; bb++) {
                        P[a][bb]         += gx[a] * gx[bb];
                        P[3 + a][3 + bb] += gy[a] * gy[bb];
                    }
            }
            // measurement update
            float R00 = KC[KC_R], R01 = KC[KC_R + 1], R11 = KC[KC_R + 2];
            float2 z = hist2[(size_t)t * B + e];
            float yx = z.x - X[0], yy = z.y - X[3];
            float S00 = P[0][0] + R00, S01 = P[0][3] + R01;
            float S10 = P[3][0] + R01, S11 = P[3][3] + R11;
            float rdet = 1.0f / (S00 * S11 - S01 * S10);
            float si00 =  S11 * rdet, si01 = -S01 * rdet;
            float si10 = -S10 * rdet, si11 =  S00 * rdet;
            float K0[6], K1[6];
#pragma unroll
            for (int i = 0; i < 6; i++) {
                K0[i] = P[i][0] * si00 + P[i][3] * si10;
                K1[i] = P[i][0] * si01 + P[i][3] * si11;
            }
#pragma unroll
            for (int i = 0; i < 6; i++) X[i] += K0[i] * yx + K1[i] * yy;
            float r0[6], r3[6];
#pragma unroll
            for (int j = 0; j < 6; j++) { r0[j] = P[0][j]; r3[j] = P[3][j]; }
#pragma unroll
            for (int i = 0; i < 6; i++)
#pragma unroll
                for (int j = 0; j < 6; j++) P[i][j] -= K0[i] * r0[j] + K1[i] * r3[j];

            // publish X(t) to the other buffer
            float* xw = base + GX + (xb ^ 1) * 512;
#pragma unroll
            for (int k = 0; k < 6; k++) xw[k * 64 + el] = X[k];
            GROUPBAR(g);
            xb ^= 1;
        }

        // ---------- prediction t = 0..LP-1 ----------
#pragma unroll 1
        for (int t = 0; t < LP; t++) {
            GROUPBAR(g);   // barA: h(t) ready

            // command = coW @ h + cob
            float cm0 = s_raw[OFF_COB + 0], cm1 = s_raw[OFF_COB + 1];
            float cm2 = s_raw[OFF_COB + 2], cm3 = s_raw[OFF_COB + 3];
            {
                const float* hb = base + GH + el;
                const float4* co4 = reinterpret_cast<const float4*>(s_raw + OFF_CO);
#pragma unroll 2
                for (int m = 0; m < 32; m++) {
                    float4 cw = co4[m];
                    float hm = hb[m * 64];
                    cm0 = fmaf(cw.x, hm, cm0);
                    cm1 = fmaf(cw.y, hm, cm1);
                    cm2 = fmaf(cw.z, hm, cm2);
                    cm3 = fmaf(cw.w, hm, cm3);
                }
            }
            // X = F X + B cmd
            {
                float x0 = X[0] + dt * X[1] + hd2 * X[2] + g0 * cm0;
                float x1 = X[1] + dt * X[2] + g1 * cm0;
                float x2 = X[2] + g2 * cm0;
                float x3 = X[3] + dt * X[4] + hd2 * X[5] + g0 * cm1;
                float x4 = X[4] + dt * X[5] + g1 * cm1;
                float x5 = X[5] + g2 * cm1;
                X[0] = x0; X[1] = x1; X[2] = x2; X[3] = x3; X[4] = x4; X[5] = x5;
            }
            float Gs[6] = {KC[KC_GT + 0] * cm2, KC[KC_GT + 1] * cm2, KC[KC_GT + 2] * cm2,
                           KC[KC_GT + 3] * cm3, KC[KC_GT + 4] * cm3, KC[KC_GT + 5] * cm3};
#pragma unroll
            for (int cc = 0; cc < 6; cc++) {
                P[0][cc] += dt * P[1][cc] + hd2 * P[2][cc];
                P[1][cc] += dt * P[2][cc];
                P[3][cc] += dt * P[4][cc] + hd2 * P[5][cc];
                P[4][cc] += dt * P[5][cc];
            }
#pragma unroll
            for (int r = 0; r < 6; r++) {
                P[r][0] += dt * P[r][1] + hd2 * P[r][2];
                P[r][1] += dt * P[r][2];
                P[r][3] += dt * P[r][4] + hd2 * P[r][5];
                P[r][4] += dt * P[r][5];
            }
#pragma unroll
            for (int i = 0; i < 6; i++)
#pragma unroll
                for (int j = 0; j < 6; j++) P[i][j] += Gs[i] * Gs[j];

            // outputs
            if (valid) {
                float sx = sqrtf(P[0][0]);
                float sy = sqrtf(P[3][3]);
                float rho = __fdividef(P[0][3] + P[3][0], 2.0f * sx * sy);
                size_t o = ((size_t)t * B + e) * 5;
                out[o + 0] = X[0];
                out[o + 1] = X[3];
                out[o + 2] = sx;
                out[o + 3] = sy;
                out[o + 4] = rho;
            }

            // publish X(t) for next LSTM step
            float* xw = base + GX + (xb ^ 1) * 512;
#pragma unroll
            for (int k = 0; k < 6; k++) xw[k * 64 + el] = X[k];
            GROUPBAR(g);   // barB
            xb ^= 1;
        }
    }
}

extern "C" void kernel_launch(void* const* d_in, const int* in_sizes, int n_in,
                              void* d_out, int out_size) {
    const float* hist  = (const float*)d_in[0];
    const float* psx   = (const float*)d_in[1];
    const float* psy   = (const float*)d_in[2];
    const float* vsx   = (const float*)d_in[3];
    const float* vsy   = (const float*)d_in[4];
    const float* asx   = (const float*)d_in[5];
    const float* asy   = (const float*)d_in[6];
    const float* jerk  = (const float*)d_in[7];
    const float* coefG = (const float*)d_in[8];
    const float* GR    = (const float*)d_in[9];
    const float* cfW   = (const float*)d_in[10];
    const float* cfb   = (const float*)d_in[11];
    const float* Wih   = (const float*)d_in[12];
    const float* Whh   = (const float*)d_in[13];
    const float* bih   = (const float*)d_in[14];
    const float* bhh   = (const float*)d_in[15];
    const float* coW   = (const float*)d_in[16];
    const float* cob   = (const float*)d_in[17];
    float* out = (float*)d_out;

    const int T = 16;
    int B  = in_sizes[0] / (2 * T);
    int LP = out_size / (B * 5);

    size_t smem = (size_t)SMEM_FLOATS * sizeof(float);  // 92288 bytes
    cudaFuncSetAttribute(kalman_lstm_kernel,
                         cudaFuncAttributeMaxDynamicSharedMemorySize, (int)smem);

    int grid = (B + 127) / 128;   // 128 elements per block
    kalman_lstm_kernel<<<grid, TB, smem>>>(
        hist, psx, psy, vsx, vsy, asx, asy, jerk, coefG, GR,
        cfW, cfb, Wih, Whh, bih, bhh, coW, cob, out, B, LP);
}